// round 6
// baseline (speedup 1.0000x reference)
#include <cuda_runtime.h>
#include <cstdint>

#define Nn 50000
#define Ee 800000
#define NEG 0.2f
#define NB_SCAN ((Nn + 255) / 256)

// ---------------- scratch (device globals; no runtime allocation) ----------
__device__ float    g_xl[(size_t)Nn * 128];
__device__ float    g_xr[(size_t)Nn * 128];
__device__ float    g_h[(size_t)Nn * 128];
__device__ float    g_lsum[Nn];
__device__ float    g_lattr[Nn];
__device__ int      g_cnt[Nn];
__device__ int      g_beg[Nn];
__device__ int      g_wp[Nn];
__device__ int      g_bsum[NB_SCAN];
__device__ int      g_boff[NB_SCAN];
__device__ int2     g_edge[Ee];            // (src, attr-bits)
__device__ uint32_t g_wtf[5 * 128 * 128];  // weights pre-converted to tf32 bits

// ---------------- helpers ---------------------------------------------------
__device__ __forceinline__ float lrelu(float v) { return (v > 0.f) ? v : NEG * v; }

__device__ __forceinline__ uint32_t to_tf32(float f) {
    uint32_t u;
    asm("cvt.rna.tf32.f32 %0, %1;" : "=r"(u) : "f"(f));
    return u;
}
__device__ __forceinline__ void cp16(void* s, const void* g, bool pred) {
    unsigned sa = (unsigned)__cvta_generic_to_shared(s);
    int sz = pred ? 16 : 0;
    asm volatile("cp.async.cg.shared.global [%0], [%1], 16, %2;\n"
                 :: "r"(sa), "l"(g), "r"(sz));
}
__device__ __forceinline__ void cp_commit() { asm volatile("cp.async.commit_group;\n"); }
__device__ __forceinline__ void cp_wait()   { asm volatile("cp.async.wait_group 0;\n"); }

__device__ __forceinline__ void mma_tf32(float c[4], uint32_t a0, uint32_t a1,
                                         uint32_t a2, uint32_t a3,
                                         uint32_t b0, uint32_t b1) {
    asm volatile(
        "mma.sync.aligned.m16n8k8.row.col.f32.tf32.tf32.f32 "
        "{%0,%1,%2,%3}, {%4,%5,%6,%7}, {%8,%9}, {%0,%1,%2,%3};\n"
        : "+f"(c[0]), "+f"(c[1]), "+f"(c[2]), "+f"(c[3])
        : "r"(a0), "r"(a1), "r"(a2), "r"(a3), "r"(b0), "r"(b1));
}

// ================= weight preconvert (once per launch) ======================
__global__ void cvtW_k(const float* __restrict__ w0, const float* __restrict__ w1,
                       const float* __restrict__ w2, const float* __restrict__ w3,
                       const float* __restrict__ w4) {
    int i = blockIdx.x * blockDim.x + threadIdx.x;
    if (i >= 5 * 16384) return;
    int slot = i >> 14, off = i & 16383;
    const float* s = (slot == 0) ? w0 : (slot == 1) ? w1 : (slot == 2) ? w2
                   : (slot == 3) ? w3 : w4;
    g_wtf[i] = to_tf32(s[off]);
}

// ================= CSR build (deterministic node-ordered scan) ==============
__global__ void hist_k(const int* __restrict__ ei, const float* __restrict__ ea) {
    int e = blockIdx.x * blockDim.x + threadIdx.x;
    if (e < Ee) {
        int dst = ei[Ee + e];
        atomicAdd(&g_cnt[dst], 1);
        atomicAdd(&g_lsum[dst], ea[e]);
    }
}
__global__ void scan1_k() {
    __shared__ int s[256];
    int t = threadIdx.x;
    int i = blockIdx.x * 256 + t;
    int v = (i < Nn) ? g_cnt[i] : 0;
    s[t] = v; __syncthreads();
#pragma unroll
    for (int off = 1; off < 256; off <<= 1) {
        int add = (t >= off) ? s[t - off] : 0;
        __syncthreads();
        s[t] += add;
        __syncthreads();
    }
    if (i < Nn) g_beg[i] = s[t] - v;             // exclusive within block
    if (t == 255) g_bsum[blockIdx.x] = s[255];
}
__global__ void scan2_k() {
    __shared__ int s[256];
    int t = threadIdx.x;
    int v = (t < NB_SCAN) ? g_bsum[t] : 0;
    s[t] = v; __syncthreads();
#pragma unroll
    for (int off = 1; off < 256; off <<= 1) {
        int add = (t >= off) ? s[t - off] : 0;
        __syncthreads();
        s[t] += add;
        __syncthreads();
    }
    if (t < NB_SCAN) g_boff[t] = s[t] - v;       // exclusive
}
__global__ void scan3_k() {
    int n = blockIdx.x * blockDim.x + threadIdx.x;
    if (n >= Nn) return;
    int beg = g_beg[n] + g_boff[n >> 8];
    g_beg[n] = beg;
    g_wp[n] = beg;
    int c = g_cnt[n];
    g_lattr[n] = (c > 0) ? g_lsum[n] / (float)c : 0.f;
}
__global__ void scatter_k(const int* __restrict__ ei, const float* __restrict__ ea) {
    int e = blockIdx.x * blockDim.x + threadIdx.x;
    if (e < Ee) {
        int dst = ei[Ee + e];
        int pos = atomicAdd(&g_wp[dst], 1);
        g_edge[pos] = make_int2(ei[e], __float_as_int(ea[e]));
    }
}

// ================= tf32 tensor-core GEMM ====================================
// B smem holds tf32 bits (g_wtf). A needs cvt only when cvtA!=0 (layer-1 raw
// x); h is stored pre-rounded so layers 2/3 pass bits straight to the MMA.
#define ASTRIDE 36
#define BSTRIDE 136
#define ASZ (128 * ASTRIDE)
#define BSZ (32 * BSTRIDE)
#define GEMM_SMEM ((ASZ + BSZ) * 2 * 4)

__global__ void __launch_bounds__(256, 2)
gemm_tc_k(const float* __restrict__ A,
          const uint32_t* __restrict__ W0, const float* __restrict__ b0, float* __restrict__ C0,
          const uint32_t* __restrict__ W1, const float* __restrict__ b1, float* __restrict__ C1,
          int M, int relu, int cvtA) {
    const uint32_t* W  = blockIdx.y ? W1 : W0;
    const float* bias  = blockIdx.y ? b1 : b0;
    float*       Cm    = blockIdx.y ? C1 : C0;

    extern __shared__ float sm[];
    float*    As[2] = { sm, sm + ASZ };
    uint32_t* Bs[2] = { (uint32_t*)(sm + 2 * ASZ), (uint32_t*)(sm + 2 * ASZ + BSZ) };

    const int t = threadIdx.x;
    const int lane = t & 31;
    const int wid = t >> 5;
    const int warp_m = wid & 3;
    const int warp_n = wid >> 2;
    const int row0 = blockIdx.x * 128;

    const int a_row = t >> 1;
    const int a_colb = (t & 1) * 16;
    const int b_k = t >> 3;
    const int b_nb = (t & 7) * 16;
    const bool a_ok = (row0 + a_row) < M;
    const float* Arow = A + (size_t)(row0 + a_row) * 128;

    float acc[2][8][4];
#pragma unroll
    for (int i = 0; i < 2; i++)
#pragma unroll
        for (int j = 0; j < 8; j++)
#pragma unroll
            for (int k = 0; k < 4; k++) acc[i][j][k] = 0.f;

#pragma unroll
    for (int q = 0; q < 4; q++) {
        cp16(&As[0][a_row * ASTRIDE + a_colb + q * 4], Arow + a_colb + q * 4, a_ok);
        cp16(&Bs[0][b_k * BSTRIDE + b_nb + q * 4], W + (size_t)b_k * 128 + b_nb + q * 4, true);
    }
    cp_commit();

    int buf = 0;
    for (int c = 0; c < 4; c++) {
        cp_wait();
        __syncthreads();
        if (c < 3) {
            int k0 = (c + 1) * 32;
            int nb = buf ^ 1;
#pragma unroll
            for (int q = 0; q < 4; q++) {
                cp16(&As[nb][a_row * ASTRIDE + a_colb + q * 4], Arow + k0 + a_colb + q * 4, a_ok);
                cp16(&Bs[nb][b_k * BSTRIDE + b_nb + q * 4], W + (size_t)(k0 + b_k) * 128 + b_nb + q * 4, true);
            }
            cp_commit();
        }
        const uint32_t* as = (const uint32_t*)As[buf];
        const uint32_t* bs = Bs[buf];
        const int ar = warp_m * 32 + (lane >> 2);
        const int ac = lane & 3;
        const int bn = warp_n * 64 + (lane >> 2);
        const int bk = lane & 3;
#pragma unroll
        for (int ks = 0; ks < 4; ks++) {
            uint32_t af[2][4];
#pragma unroll
            for (int mt = 0; mt < 2; mt++) {
                const uint32_t* ap = as + (ar + mt * 16) * ASTRIDE + ks * 8 + ac;
                uint32_t r0 = ap[0];
                uint32_t r1 = ap[8 * ASTRIDE];
                uint32_t r2 = ap[4];
                uint32_t r3 = ap[8 * ASTRIDE + 4];
                if (cvtA) {
                    r0 = to_tf32(__uint_as_float(r0));
                    r1 = to_tf32(__uint_as_float(r1));
                    r2 = to_tf32(__uint_as_float(r2));
                    r3 = to_tf32(__uint_as_float(r3));
                }
                af[mt][0] = r0; af[mt][1] = r1; af[mt][2] = r2; af[mt][3] = r3;
            }
#pragma unroll
            for (int nt = 0; nt < 8; nt++) {
                const uint32_t* bp = bs + (ks * 8 + bk) * BSTRIDE + bn + nt * 8;
                uint32_t bf0 = bp[0];
                uint32_t bf1 = bp[4 * BSTRIDE];
                mma_tf32(acc[0][nt], af[0][0], af[0][1], af[0][2], af[0][3], bf0, bf1);
                mma_tf32(acc[1][nt], af[1][0], af[1][1], af[1][2], af[1][3], bf0, bf1);
            }
        }
        __syncthreads();
        buf ^= 1;
    }

    const int crow = row0 + warp_m * 32 + (lane >> 2);
    const int ccol0 = warp_n * 64 + (lane & 3) * 2;
#pragma unroll
    for (int nt = 0; nt < 8; nt++) {
        int col = ccol0 + nt * 8;
        float bx = bias[col], by = bias[col + 1];
#pragma unroll
        for (int mt = 0; mt < 2; mt++) {
            int r0 = crow + mt * 16;
            float v0 = acc[mt][nt][0] + bx, v1 = acc[mt][nt][1] + by;
            float v2 = acc[mt][nt][2] + bx, v3 = acc[mt][nt][3] + by;
            if (relu) {
                v0 = fmaxf(v0, 0.f); v1 = fmaxf(v1, 0.f);
                v2 = fmaxf(v2, 0.f); v3 = fmaxf(v3, 0.f);
            }
            if (r0 < M)     *(float2*)(Cm + (size_t)r0 * 128 + col)       = make_float2(v0, v1);
            if (r0 + 8 < M) *(float2*)(Cm + (size_t)(r0 + 8) * 128 + col) = make_float2(v2, v3);
        }
    }
}

// ================= per-node fused GAT layer =================================
// One warp per dst node; segments are node-ordered (scan CSR) so consecutive
// warps stream consecutive edge memory. h stored pre-rounded to tf32 bits.
__global__ void __launch_bounds__(256)
node_agg_k(const float* __restrict__ We, const float* __restrict__ att,
           const float* __restrict__ bo) {
    int n = (blockIdx.x * blockDim.x + threadIdx.x) >> 5;
    int lane = threadIdx.x & 31;
    if (n >= Nn) return;

    float4 br  = *(const float4*)(g_xr + (size_t)n * 128 + lane * 4);
    float4 w4  = *(const float4*)(We + lane * 4);
    float4 at4 = *(const float4*)(att + lane * 4);

    float4 acc = make_float4(0.f, 0.f, 0.f, 0.f);
    float ssum = 0.f;

    const int beg = g_beg[n];
    const int end = beg + g_cnt[n];

    // self loop (kept out of the edge array)
    {
        float4 a = *(const float4*)(g_xl + (size_t)n * 128 + lane * 4);
        float attr = g_lattr[n];
        float m0 = lrelu(a.x + br.x + attr * w4.x);
        float m1 = lrelu(a.y + br.y + attr * w4.y);
        float m2 = lrelu(a.z + br.z + attr * w4.z);
        float m3 = lrelu(a.w + br.w + attr * w4.w);
        float p = m0 * at4.x + m1 * at4.y + m2 * at4.z + m3 * at4.w;
        p += __shfl_xor_sync(0xFFFFFFFFu, p, 1);
        p += __shfl_xor_sync(0xFFFFFFFFu, p, 2);
        p += __shfl_xor_sync(0xFFFFFFFFu, p, 4);
        float e = __expf(p);
        acc.x = fmaf(e, a.x, acc.x);
        acc.y = fmaf(e, a.y, acc.y);
        acc.z = fmaf(e, a.z, acc.z);
        acc.w = fmaf(e, a.w, acc.w);
        ssum += e;
    }

    for (int j = beg; j < end; j++) {
        int2 ed = g_edge[j];
        float attr = __int_as_float(ed.y);
        float4 a = *(const float4*)(g_xl + (size_t)ed.x * 128 + lane * 4);
        float m0 = lrelu(a.x + br.x + attr * w4.x);
        float m1 = lrelu(a.y + br.y + attr * w4.y);
        float m2 = lrelu(a.z + br.z + attr * w4.z);
        float m3 = lrelu(a.w + br.w + attr * w4.w);
        float p = m0 * at4.x + m1 * at4.y + m2 * at4.z + m3 * at4.w;
        p += __shfl_xor_sync(0xFFFFFFFFu, p, 1);
        p += __shfl_xor_sync(0xFFFFFFFFu, p, 2);
        p += __shfl_xor_sync(0xFFFFFFFFu, p, 4);
        float e = __expf(p);
        acc.x = fmaf(e, a.x, acc.x);
        acc.y = fmaf(e, a.y, acc.y);
        acc.z = fmaf(e, a.z, acc.z);
        acc.w = fmaf(e, a.w, acc.w);
        ssum += e;
    }

    float inv = 1.f / (ssum + 1e-16f);
    float4 bo4 = *(const float4*)(bo + lane * 4);
    uint4 o;
    o.x = to_tf32(fmaxf(acc.x * inv + bo4.x, 0.f));
    o.y = to_tf32(fmaxf(acc.y * inv + bo4.y, 0.f));
    o.z = to_tf32(fmaxf(acc.z * inv + bo4.z, 0.f));
    o.w = to_tf32(fmaxf(acc.w * inv + bo4.w, 0.f));
    *(uint4*)(g_h + (size_t)n * 128 + lane * 4) = o;
}

// ================= launch ===================================================
extern "C" void kernel_launch(void* const* d_in, const int* in_sizes, int n_in,
                              void* d_out, int out_size) {
    const float* x    = (const float*)d_in[0];
    const int*   ei   = (const int*)  d_in[1];
    const float* ea   = (const float*)d_in[2];
    const float* Wl1  = (const float*)d_in[3];
    const float* bl1  = (const float*)d_in[4];
    const float* Wr1  = (const float*)d_in[5];
    const float* br1  = (const float*)d_in[6];
    const float* We1  = (const float*)d_in[7];
    const float* att1 = (const float*)d_in[8];
    const float* bo1  = (const float*)d_in[9];
    const float* Wl2  = (const float*)d_in[10];
    const float* bl2  = (const float*)d_in[11];
    const float* Wr2  = (const float*)d_in[12];
    const float* br2  = (const float*)d_in[13];
    const float* We2  = (const float*)d_in[14];
    const float* att2 = (const float*)d_in[15];
    const float* bo2  = (const float*)d_in[16];
    const float* Wlin = (const float*)d_in[17];
    const float* blin = (const float*)d_in[18];
    float* out = (float*)d_out;

    float *pxl, *pxr, *ph;
    uint32_t* pw;
    void *pcnt, *plsum;
    cudaGetSymbolAddress((void**)&pxl, g_xl);
    cudaGetSymbolAddress((void**)&pxr, g_xr);
    cudaGetSymbolAddress((void**)&ph,  g_h);
    cudaGetSymbolAddress((void**)&pw,  g_wtf);
    cudaGetSymbolAddress(&pcnt,  g_cnt);
    cudaGetSymbolAddress(&plsum, g_lsum);

    static int smem_set = 0;
    if (!smem_set) {
        cudaFuncSetAttribute(gemm_tc_k, cudaFuncAttributeMaxDynamicSharedMemorySize, GEMM_SMEM);
        smem_set = 1;
    }

    const int TB = 256;
    const int gb_n  = (Nn + TB - 1) / TB;
    const int gb_e  = (Ee + TB - 1) / TB;
    const int gb_w  = (5 * 16384 + TB - 1) / TB;
    const int gb_gemm = (Nn + 127) / 128;
    const int gb_node = (Nn * 32 + TB - 1) / TB;
    dim3 grid2(gb_gemm, 2), grid1(gb_gemm, 1);

    const uint32_t* wl1 = pw + 0 * 16384;
    const uint32_t* wr1 = pw + 1 * 16384;
    const uint32_t* wl2 = pw + 2 * 16384;
    const uint32_t* wr2 = pw + 3 * 16384;
    const uint32_t* wli = pw + 4 * 16384;

    // ---- CSR build (node-ordered) + weight preconvert ----
    cudaMemsetAsync(pcnt,  0, Nn * sizeof(int));
    cudaMemsetAsync(plsum, 0, Nn * sizeof(float));
    cvtW_k<<<gb_w, TB>>>(Wl1, Wr1, Wl2, Wr2, Wlin);
    hist_k<<<gb_e, TB>>>(ei, ea);
    scan1_k<<<NB_SCAN, 256>>>();
    scan2_k<<<1, 256>>>();
    scan3_k<<<gb_n, TB>>>();
    scatter_k<<<gb_e, TB>>>(ei, ea);

    // ---- layer 1 (A = raw x -> cvtA=1) ----
    gemm_tc_k<<<grid2, TB, GEMM_SMEM>>>(x, wl1, bl1, pxl, wr1, br1, pxr, Nn, 0, 1);
    node_agg_k<<<gb_node, TB>>>(We1, att1, bo1);

    // ---- layer 2 (A = pre-rounded h -> cvtA=0) ----
    gemm_tc_k<<<grid2, TB, GEMM_SMEM>>>(ph, wl2, bl2, pxl, wr2, br2, pxr, Nn, 0, 0);
    node_agg_k<<<gb_node, TB>>>(We2, att2, bo2);

    // ---- final linear + relu -> d_out ----
    gemm_tc_k<<<grid1, TB, GEMM_SMEM>>>(ph, wli, blin, out, wli, blin, out, Nn, 1, 0);
}

// round 7
// speedup vs baseline: 1.0133x; 1.0133x over previous
#include <cuda_runtime.h>
#include <cstdint>

#define Nn 50000
#define Ee 800000
#define NEG 0.2f
#define NB_SCAN ((Nn + 255) / 256)

// ---------------- scratch (device globals; no runtime allocation) ----------
__device__ float    g_xl[(size_t)Nn * 128];
__device__ float    g_xr[(size_t)Nn * 128];
__device__ float    g_h[(size_t)Nn * 128];
__device__ float    g_lsum[Nn];
__device__ float    g_lattr[Nn];
__device__ int      g_cnt[Nn];
__device__ int      g_beg[Nn];
__device__ int      g_wp[Nn];
__device__ int      g_bsum[NB_SCAN];
__device__ int      g_boff[NB_SCAN];
__device__ int2     g_edge[Ee];            // (src, attr-bits)
__device__ uint32_t g_wtf[5 * 128 * 128];  // weights pre-converted to tf32 bits

// ---------------- helpers ---------------------------------------------------
__device__ __forceinline__ float lrelu(float v) { return (v > 0.f) ? v : NEG * v; }

__device__ __forceinline__ uint32_t to_tf32(float f) {
    uint32_t u;
    asm("cvt.rna.tf32.f32 %0, %1;" : "=r"(u) : "f"(f));
    return u;
}
__device__ __forceinline__ void cp16(void* s, const void* g, bool pred) {
    unsigned sa = (unsigned)__cvta_generic_to_shared(s);
    int sz = pred ? 16 : 0;
    asm volatile("cp.async.cg.shared.global [%0], [%1], 16, %2;\n"
                 :: "r"(sa), "l"(g), "r"(sz));
}
__device__ __forceinline__ void cp_commit() { asm volatile("cp.async.commit_group;\n"); }
__device__ __forceinline__ void cp_wait()   { asm volatile("cp.async.wait_group 0;\n"); }

__device__ __forceinline__ void mma_tf32(float c[4], uint32_t a0, uint32_t a1,
                                         uint32_t a2, uint32_t a3,
                                         uint32_t b0, uint32_t b1) {
    asm volatile(
        "mma.sync.aligned.m16n8k8.row.col.f32.tf32.tf32.f32 "
        "{%0,%1,%2,%3}, {%4,%5,%6,%7}, {%8,%9}, {%0,%1,%2,%3};\n"
        : "+f"(c[0]), "+f"(c[1]), "+f"(c[2]), "+f"(c[3])
        : "r"(a0), "r"(a1), "r"(a2), "r"(a3), "r"(b0), "r"(b1));
}

// ================= weight preconvert (once per launch) ======================
__global__ void cvtW_k(const float* __restrict__ w0, const float* __restrict__ w1,
                       const float* __restrict__ w2, const float* __restrict__ w3,
                       const float* __restrict__ w4) {
    int i = blockIdx.x * blockDim.x + threadIdx.x;
    if (i >= 5 * 16384) return;
    int slot = i >> 14, off = i & 16383;
    const float* s = (slot == 0) ? w0 : (slot == 1) ? w1 : (slot == 2) ? w2
                   : (slot == 3) ? w3 : w4;
    g_wtf[i] = to_tf32(s[off]);
}

// ================= CSR build (deterministic node-ordered scan) ==============
__global__ void hist_k(const int* __restrict__ ei, const float* __restrict__ ea) {
    int e = blockIdx.x * blockDim.x + threadIdx.x;
    if (e < Ee) {
        int dst = ei[Ee + e];
        atomicAdd(&g_cnt[dst], 1);
        atomicAdd(&g_lsum[dst], ea[e]);
    }
}
__global__ void scan1_k() {
    __shared__ int s[256];
    int t = threadIdx.x;
    int i = blockIdx.x * 256 + t;
    int v = (i < Nn) ? g_cnt[i] : 0;
    s[t] = v; __syncthreads();
#pragma unroll
    for (int off = 1; off < 256; off <<= 1) {
        int add = (t >= off) ? s[t - off] : 0;
        __syncthreads();
        s[t] += add;
        __syncthreads();
    }
    if (i < Nn) g_beg[i] = s[t] - v;             // exclusive within block
    if (t == 255) g_bsum[blockIdx.x] = s[255];
}
// one-warp serial-carry scan over NB_SCAN block sums
__global__ void scan2_k() {
    int lane = threadIdx.x;
    int carry = 0;
    for (int base = 0; base < NB_SCAN; base += 32) {
        int i = base + lane;
        int v = (i < NB_SCAN) ? g_bsum[i] : 0;
        int s = v;
#pragma unroll
        for (int off = 1; off < 32; off <<= 1) {
            int u = __shfl_up_sync(0xFFFFFFFFu, s, off);
            if (lane >= off) s += u;
        }
        if (i < NB_SCAN) g_boff[i] = carry + s - v;
        carry += __shfl_sync(0xFFFFFFFFu, s, 31);
    }
}
__global__ void scan3_k() {
    int n = blockIdx.x * blockDim.x + threadIdx.x;
    if (n >= Nn) return;
    int beg = g_beg[n] + g_boff[n >> 8];
    g_beg[n] = beg;
    g_wp[n] = beg;
    int c = g_cnt[n];
    g_lattr[n] = (c > 0) ? g_lsum[n] / (float)c : 0.f;
}
__global__ void scatter_k(const int* __restrict__ ei, const float* __restrict__ ea) {
    int e = blockIdx.x * blockDim.x + threadIdx.x;
    if (e < Ee) {
        int dst = ei[Ee + e];
        int pos = atomicAdd(&g_wp[dst], 1);
        g_edge[pos] = make_int2(ei[e], __float_as_int(ea[e]));
    }
}

// ================= tf32 tensor-core GEMM ====================================
#define ASTRIDE 36
#define BSTRIDE 136
#define ASZ (128 * ASTRIDE)
#define BSZ (32 * BSTRIDE)
#define GEMM_SMEM ((ASZ + BSZ) * 2 * 4)

__global__ void __launch_bounds__(256, 2)
gemm_tc_k(const float* __restrict__ A,
          const uint32_t* __restrict__ W0, const float* __restrict__ b0, float* __restrict__ C0,
          const uint32_t* __restrict__ W1, const float* __restrict__ b1, float* __restrict__ C1,
          int M, int relu, int cvtA) {
    const uint32_t* W  = blockIdx.y ? W1 : W0;
    const float* bias  = blockIdx.y ? b1 : b0;
    float*       Cm    = blockIdx.y ? C1 : C0;

    extern __shared__ float sm[];
    float*    As[2] = { sm, sm + ASZ };
    uint32_t* Bs[2] = { (uint32_t*)(sm + 2 * ASZ), (uint32_t*)(sm + 2 * ASZ + BSZ) };

    const int t = threadIdx.x;
    const int lane = t & 31;
    const int wid = t >> 5;
    const int warp_m = wid & 3;
    const int warp_n = wid >> 2;
    const int row0 = blockIdx.x * 128;

    const int a_row = t >> 1;
    const int a_colb = (t & 1) * 16;
    const int b_k = t >> 3;
    const int b_nb = (t & 7) * 16;
    const bool a_ok = (row0 + a_row) < M;
    const float* Arow = A + (size_t)(row0 + a_row) * 128;

    float acc[2][8][4];
#pragma unroll
    for (int i = 0; i < 2; i++)
#pragma unroll
        for (int j = 0; j < 8; j++)
#pragma unroll
            for (int k = 0; k < 4; k++) acc[i][j][k] = 0.f;

#pragma unroll
    for (int q = 0; q < 4; q++) {
        cp16(&As[0][a_row * ASTRIDE + a_colb + q * 4], Arow + a_colb + q * 4, a_ok);
        cp16(&Bs[0][b_k * BSTRIDE + b_nb + q * 4], W + (size_t)b_k * 128 + b_nb + q * 4, true);
    }
    cp_commit();

    int buf = 0;
    for (int c = 0; c < 4; c++) {
        cp_wait();
        __syncthreads();
        if (c < 3) {
            int k0 = (c + 1) * 32;
            int nb = buf ^ 1;
#pragma unroll
            for (int q = 0; q < 4; q++) {
                cp16(&As[nb][a_row * ASTRIDE + a_colb + q * 4], Arow + k0 + a_colb + q * 4, a_ok);
                cp16(&Bs[nb][b_k * BSTRIDE + b_nb + q * 4], W + (size_t)(k0 + b_k) * 128 + b_nb + q * 4, true);
            }
            cp_commit();
        }
        const uint32_t* as = (const uint32_t*)As[buf];
        const uint32_t* bs = Bs[buf];
        const int ar = warp_m * 32 + (lane >> 2);
        const int ac = lane & 3;
        const int bn = warp_n * 64 + (lane >> 2);
        const int bk = lane & 3;
#pragma unroll
        for (int ks = 0; ks < 4; ks++) {
            uint32_t af[2][4];
#pragma unroll
            for (int mt = 0; mt < 2; mt++) {
                const uint32_t* ap = as + (ar + mt * 16) * ASTRIDE + ks * 8 + ac;
                uint32_t r0 = ap[0];
                uint32_t r1 = ap[8 * ASTRIDE];
                uint32_t r2 = ap[4];
                uint32_t r3 = ap[8 * ASTRIDE + 4];
                if (cvtA) {
                    r0 = to_tf32(__uint_as_float(r0));
                    r1 = to_tf32(__uint_as_float(r1));
                    r2 = to_tf32(__uint_as_float(r2));
                    r3 = to_tf32(__uint_as_float(r3));
                }
                af[mt][0] = r0; af[mt][1] = r1; af[mt][2] = r2; af[mt][3] = r3;
            }
#pragma unroll
            for (int nt = 0; nt < 8; nt++) {
                const uint32_t* bp = bs + (ks * 8 + bk) * BSTRIDE + bn + nt * 8;
                uint32_t bf0 = bp[0];
                uint32_t bf1 = bp[4 * BSTRIDE];
                mma_tf32(acc[0][nt], af[0][0], af[0][1], af[0][2], af[0][3], bf0, bf1);
                mma_tf32(acc[1][nt], af[1][0], af[1][1], af[1][2], af[1][3], bf0, bf1);
            }
        }
        __syncthreads();
        buf ^= 1;
    }

    const int crow = row0 + warp_m * 32 + (lane >> 2);
    const int ccol0 = warp_n * 64 + (lane & 3) * 2;
#pragma unroll
    for (int nt = 0; nt < 8; nt++) {
        int col = ccol0 + nt * 8;
        float bx = bias[col], by = bias[col + 1];
#pragma unroll
        for (int mt = 0; mt < 2; mt++) {
            int r0 = crow + mt * 16;
            float v0 = acc[mt][nt][0] + bx, v1 = acc[mt][nt][1] + by;
            float v2 = acc[mt][nt][2] + bx, v3 = acc[mt][nt][3] + by;
            if (relu) {
                v0 = fmaxf(v0, 0.f); v1 = fmaxf(v1, 0.f);
                v2 = fmaxf(v2, 0.f); v3 = fmaxf(v3, 0.f);
            }
            if (r0 < M)     *(float2*)(Cm + (size_t)r0 * 128 + col)       = make_float2(v0, v1);
            if (r0 + 8 < M) *(float2*)(Cm + (size_t)(r0 + 8) * 128 + col) = make_float2(v2, v3);
        }
    }
}

// ================= per-node fused GAT layer (dual-stream ILP) ===============
// One warp per dst node. Edge list split into two independent accumulator
// chains interleaved instruction-wise: 2 gathers / 6 shuffles / 2 exps in
// flight instead of 1/3/1. 128-thread blocks for finer retirement.
__global__ void __launch_bounds__(128)
node_agg_k(const float* __restrict__ We, const float* __restrict__ att,
           const float* __restrict__ bo) {
    int n = (blockIdx.x * blockDim.x + threadIdx.x) >> 5;
    int lane = threadIdx.x & 31;
    if (n >= Nn) return;

    float4 br  = *(const float4*)(g_xr + (size_t)n * 128 + lane * 4);
    float4 w4  = *(const float4*)(We + lane * 4);
    float4 at4 = *(const float4*)(att + lane * 4);

    float4 accA = make_float4(0.f, 0.f, 0.f, 0.f);
    float4 accB = make_float4(0.f, 0.f, 0.f, 0.f);
    float ssA = 0.f, ssB = 0.f;

    const int beg = g_beg[n];
    const int cnt = g_cnt[n];
    const int half = cnt >> 1;
    const int mid = beg + half;

    // self loop -> stream A
    {
        float4 a = *(const float4*)(g_xl + (size_t)n * 128 + lane * 4);
        float attr = g_lattr[n];
        float m0 = lrelu(a.x + br.x + attr * w4.x);
        float m1 = lrelu(a.y + br.y + attr * w4.y);
        float m2 = lrelu(a.z + br.z + attr * w4.z);
        float m3 = lrelu(a.w + br.w + attr * w4.w);
        float p = m0 * at4.x + m1 * at4.y + m2 * at4.z + m3 * at4.w;
        p += __shfl_xor_sync(0xFFFFFFFFu, p, 1);
        p += __shfl_xor_sync(0xFFFFFFFFu, p, 2);
        p += __shfl_xor_sync(0xFFFFFFFFu, p, 4);
        float e = __expf(p);
        accA.x = fmaf(e, a.x, accA.x);
        accA.y = fmaf(e, a.y, accA.y);
        accA.z = fmaf(e, a.z, accA.z);
        accA.w = fmaf(e, a.w, accA.w);
        ssA += e;
    }

    for (int k = 0; k < half; k++) {
        int2 edA = g_edge[beg + k];
        int2 edB = g_edge[mid + k];
        float4 aA = *(const float4*)(g_xl + (size_t)edA.x * 128 + lane * 4);
        float4 aB = *(const float4*)(g_xl + (size_t)edB.x * 128 + lane * 4);
        float atA = __int_as_float(edA.y);
        float atB = __int_as_float(edB.y);
        float pA, pB;
        {
            float m0 = lrelu(aA.x + br.x + atA * w4.x);
            float n0 = lrelu(aB.x + br.x + atB * w4.x);
            float m1 = lrelu(aA.y + br.y + atA * w4.y);
            float n1 = lrelu(aB.y + br.y + atB * w4.y);
            float m2 = lrelu(aA.z + br.z + atA * w4.z);
            float n2 = lrelu(aB.z + br.z + atB * w4.z);
            float m3 = lrelu(aA.w + br.w + atA * w4.w);
            float n3 = lrelu(aB.w + br.w + atB * w4.w);
            pA = m0 * at4.x + m1 * at4.y + m2 * at4.z + m3 * at4.w;
            pB = n0 * at4.x + n1 * at4.y + n2 * at4.z + n3 * at4.w;
        }
        pA += __shfl_xor_sync(0xFFFFFFFFu, pA, 1);
        pB += __shfl_xor_sync(0xFFFFFFFFu, pB, 1);
        pA += __shfl_xor_sync(0xFFFFFFFFu, pA, 2);
        pB += __shfl_xor_sync(0xFFFFFFFFu, pB, 2);
        pA += __shfl_xor_sync(0xFFFFFFFFu, pA, 4);
        pB += __shfl_xor_sync(0xFFFFFFFFu, pB, 4);
        float eA = __expf(pA);
        float eB = __expf(pB);
        accA.x = fmaf(eA, aA.x, accA.x);
        accB.x = fmaf(eB, aB.x, accB.x);
        accA.y = fmaf(eA, aA.y, accA.y);
        accB.y = fmaf(eB, aB.y, accB.y);
        accA.z = fmaf(eA, aA.z, accA.z);
        accB.z = fmaf(eB, aB.z, accB.z);
        accA.w = fmaf(eA, aA.w, accA.w);
        accB.w = fmaf(eB, aB.w, accB.w);
        ssA += eA;
        ssB += eB;
    }
    if (cnt & 1) {           // odd remainder: element beg + 2*half
        int2 ed = g_edge[beg + 2 * half];
        float attr = __int_as_float(ed.y);
        float4 a = *(const float4*)(g_xl + (size_t)ed.x * 128 + lane * 4);
        float m0 = lrelu(a.x + br.x + attr * w4.x);
        float m1 = lrelu(a.y + br.y + attr * w4.y);
        float m2 = lrelu(a.z + br.z + attr * w4.z);
        float m3 = lrelu(a.w + br.w + attr * w4.w);
        float p = m0 * at4.x + m1 * at4.y + m2 * at4.z + m3 * at4.w;
        p += __shfl_xor_sync(0xFFFFFFFFu, p, 1);
        p += __shfl_xor_sync(0xFFFFFFFFu, p, 2);
        p += __shfl_xor_sync(0xFFFFFFFFu, p, 4);
        float e = __expf(p);
        accB.x = fmaf(e, a.x, accB.x);
        accB.y = fmaf(e, a.y, accB.y);
        accB.z = fmaf(e, a.z, accB.z);
        accB.w = fmaf(e, a.w, accB.w);
        ssB += e;
    }

    float inv = 1.f / (ssA + ssB + 1e-16f);
    float4 bo4 = *(const float4*)(bo + lane * 4);
    uint4 o;
    o.x = to_tf32(fmaxf((accA.x + accB.x) * inv + bo4.x, 0.f));
    o.y = to_tf32(fmaxf((accA.y + accB.y) * inv + bo4.y, 0.f));
    o.z = to_tf32(fmaxf((accA.z + accB.z) * inv + bo4.z, 0.f));
    o.w = to_tf32(fmaxf((accA.w + accB.w) * inv + bo4.w, 0.f));
    *(uint4*)(g_h + (size_t)n * 128 + lane * 4) = o;
}

// ================= launch ===================================================
extern "C" void kernel_launch(void* const* d_in, const int* in_sizes, int n_in,
                              void* d_out, int out_size) {
    const float* x    = (const float*)d_in[0];
    const int*   ei   = (const int*)  d_in[1];
    const float* ea   = (const float*)d_in[2];
    const float* Wl1  = (const float*)d_in[3];
    const float* bl1  = (const float*)d_in[4];
    const float* Wr1  = (const float*)d_in[5];
    const float* br1  = (const float*)d_in[6];
    const float* We1  = (const float*)d_in[7];
    const float* att1 = (const float*)d_in[8];
    const float* bo1  = (const float*)d_in[9];
    const float* Wl2  = (const float*)d_in[10];
    const float* bl2  = (const float*)d_in[11];
    const float* Wr2  = (const float*)d_in[12];
    const float* br2  = (const float*)d_in[13];
    const float* We2  = (const float*)d_in[14];
    const float* att2 = (const float*)d_in[15];
    const float* bo2  = (const float*)d_in[16];
    const float* Wlin = (const float*)d_in[17];
    const float* blin = (const float*)d_in[18];
    float* out = (float*)d_out;

    float *pxl, *pxr, *ph;
    uint32_t* pw;
    void *pcnt, *plsum;
    cudaGetSymbolAddress((void**)&pxl, g_xl);
    cudaGetSymbolAddress((void**)&pxr, g_xr);
    cudaGetSymbolAddress((void**)&ph,  g_h);
    cudaGetSymbolAddress((void**)&pw,  g_wtf);
    cudaGetSymbolAddress(&pcnt,  g_cnt);
    cudaGetSymbolAddress(&plsum, g_lsum);

    static int smem_set = 0;
    if (!smem_set) {
        cudaFuncSetAttribute(gemm_tc_k, cudaFuncAttributeMaxDynamicSharedMemorySize, GEMM_SMEM);
        smem_set = 1;
    }

    const int TB = 256;
    const int gb_n  = (Nn + TB - 1) / TB;
    const int gb_e  = (Ee + TB - 1) / TB;
    const int gb_w  = (5 * 16384 + TB - 1) / TB;
    const int gb_gemm = (Nn + 127) / 128;
    const int gb_node = (Nn * 32 + 127) / 128;     // 128-thread blocks
    dim3 grid2(gb_gemm, 2), grid1(gb_gemm, 1);

    const uint32_t* wl1 = pw + 0 * 16384;
    const uint32_t* wr1 = pw + 1 * 16384;
    const uint32_t* wl2 = pw + 2 * 16384;
    const uint32_t* wr2 = pw + 3 * 16384;
    const uint32_t* wli = pw + 4 * 16384;

    // ---- CSR build (node-ordered) + weight preconvert ----
    cudaMemsetAsync(pcnt,  0, Nn * sizeof(int));
    cudaMemsetAsync(plsum, 0, Nn * sizeof(float));
    cvtW_k<<<gb_w, TB>>>(Wl1, Wr1, Wl2, Wr2, Wlin);
    hist_k<<<gb_e, TB>>>(ei, ea);
    scan1_k<<<NB_SCAN, 256>>>();
    scan2_k<<<1, 32>>>();
    scan3_k<<<gb_n, TB>>>();
    scatter_k<<<gb_e, TB>>>(ei, ea);

    // ---- layer 1 (A = raw x -> cvtA=1) ----
    gemm_tc_k<<<grid2, TB, GEMM_SMEM>>>(x, wl1, bl1, pxl, wr1, br1, pxr, Nn, 0, 1);
    node_agg_k<<<gb_node, 128>>>(We1, att1, bo1);

    // ---- layer 2 (A = pre-rounded h -> cvtA=0) ----
    gemm_tc_k<<<grid2, TB, GEMM_SMEM>>>(ph, wl2, bl2, pxl, wr2, br2, pxr, Nn, 0, 0);
    node_agg_k<<<gb_node, 128>>>(We2, att2, bo2);

    // ---- final linear + relu -> d_out ----
    gemm_tc_k<<<grid1, TB, GEMM_SMEM>>>(ph, wli, blin, out, wli, blin, out, Nn, 1, 0);
}

// round 8
// speedup vs baseline: 1.0739x; 1.0598x over previous
#include <cuda_runtime.h>
#include <cuda_fp16.h>
#include <cstdint>

#define Nn 50000
#define Ee 800000
#define NEG 0.2f
#define NB_SCAN ((Nn + 255) / 256)

// ---------------- scratch (device globals; no runtime allocation) ----------
__device__ uint32_t g_xl16[(size_t)Nn * 64];   // xl in half2 pairs (128 ch = 64 uints)
__device__ float    g_xr[(size_t)Nn * 128];
__device__ float    g_h[(size_t)Nn * 128];
__device__ float    g_lsum[Nn];
__device__ float    g_lattr[Nn];
__device__ int      g_cnt[Nn];
__device__ int      g_beg[Nn];
__device__ int      g_wp[Nn];
__device__ int      g_bsum[NB_SCAN];
__device__ int      g_boff[NB_SCAN];
__device__ int2     g_edge[Ee];                // (src, attr-bits)
__device__ uint32_t g_wtf[5 * 128 * 128];      // weights pre-converted to tf32 bits

// ---------------- helpers ---------------------------------------------------
__device__ __forceinline__ float lrelu(float v) { return (v > 0.f) ? v : NEG * v; }

__device__ __forceinline__ uint32_t to_tf32(float f) {
    uint32_t u;
    asm("cvt.rna.tf32.f32 %0, %1;" : "=r"(u) : "f"(f));
    return u;
}
__device__ __forceinline__ void cp16(void* s, const void* g, bool pred) {
    unsigned sa = (unsigned)__cvta_generic_to_shared(s);
    int sz = pred ? 16 : 0;
    asm volatile("cp.async.cg.shared.global [%0], [%1], 16, %2;\n"
                 :: "r"(sa), "l"(g), "r"(sz));
}
__device__ __forceinline__ void cp_commit() { asm volatile("cp.async.commit_group;\n"); }
__device__ __forceinline__ void cp_wait()   { asm volatile("cp.async.wait_group 0;\n"); }

__device__ __forceinline__ void mma_tf32(float c[4], uint32_t a0, uint32_t a1,
                                         uint32_t a2, uint32_t a3,
                                         uint32_t b0, uint32_t b1) {
    asm volatile(
        "mma.sync.aligned.m16n8k8.row.col.f32.tf32.tf32.f32 "
        "{%0,%1,%2,%3}, {%4,%5,%6,%7}, {%8,%9}, {%0,%1,%2,%3};\n"
        : "+f"(c[0]), "+f"(c[1]), "+f"(c[2]), "+f"(c[3])
        : "r"(a0), "r"(a1), "r"(a2), "r"(a3), "r"(b0), "r"(b1));
}
__device__ __forceinline__ float4 ld_xl16(int node, int lane) {
    uint2 u = *(const uint2*)(g_xl16 + (size_t)node * 64 + lane * 2);
    float2 lo = __half22float2(*(const __half2*)&u.x);
    float2 hi = __half22float2(*(const __half2*)&u.y);
    return make_float4(lo.x, lo.y, hi.x, hi.y);
}

// ================= weight preconvert (once per launch) ======================
__global__ void cvtW_k(const float* __restrict__ w0, const float* __restrict__ w1,
                       const float* __restrict__ w2, const float* __restrict__ w3,
                       const float* __restrict__ w4) {
    int i = blockIdx.x * blockDim.x + threadIdx.x;
    if (i >= 5 * 16384) return;
    int slot = i >> 14, off = i & 16383;
    const float* s = (slot == 0) ? w0 : (slot == 1) ? w1 : (slot == 2) ? w2
                   : (slot == 3) ? w3 : w4;
    g_wtf[i] = to_tf32(s[off]);
}

// ================= CSR build (deterministic node-ordered scan) ==============
__global__ void hist_k(const int* __restrict__ ei, const float* __restrict__ ea) {
    int e = blockIdx.x * blockDim.x + threadIdx.x;
    if (e < Ee) {
        int dst = ei[Ee + e];
        atomicAdd(&g_cnt[dst], 1);
        atomicAdd(&g_lsum[dst], ea[e]);
    }
}
__global__ void scan1_k() {
    __shared__ int s[256];
    int t = threadIdx.x;
    int i = blockIdx.x * 256 + t;
    int v = (i < Nn) ? g_cnt[i] : 0;
    s[t] = v; __syncthreads();
#pragma unroll
    for (int off = 1; off < 256; off <<= 1) {
        int add = (t >= off) ? s[t - off] : 0;
        __syncthreads();
        s[t] += add;
        __syncthreads();
    }
    if (i < Nn) g_beg[i] = s[t] - v;
    if (t == 255) g_bsum[blockIdx.x] = s[255];
}
__global__ void scan2_k() {
    int lane = threadIdx.x;
    int carry = 0;
    for (int base = 0; base < NB_SCAN; base += 32) {
        int i = base + lane;
        int v = (i < NB_SCAN) ? g_bsum[i] : 0;
        int s = v;
#pragma unroll
        for (int off = 1; off < 32; off <<= 1) {
            int u = __shfl_up_sync(0xFFFFFFFFu, s, off);
            if (lane >= off) s += u;
        }
        if (i < NB_SCAN) g_boff[i] = carry + s - v;
        carry += __shfl_sync(0xFFFFFFFFu, s, 31);
    }
}
__global__ void scan3_k() {
    int n = blockIdx.x * blockDim.x + threadIdx.x;
    if (n >= Nn) return;
    int beg = g_beg[n] + g_boff[n >> 8];
    g_beg[n] = beg;
    g_wp[n] = beg;
    int c = g_cnt[n];
    g_lattr[n] = (c > 0) ? g_lsum[n] / (float)c : 0.f;
}
__global__ void scatter_k(const int* __restrict__ ei, const float* __restrict__ ea) {
    int e = blockIdx.x * blockDim.x + threadIdx.x;
    if (e < Ee) {
        int dst = ei[Ee + e];
        int pos = atomicAdd(&g_wp[dst], 1);
        g_edge[pos] = make_int2(ei[e], __float_as_int(ea[e]));
    }
}

// ================= tf32 tensor-core GEMM ====================================
// c0half: blockIdx.y==0 output stored as packed half2 (for the edge-gather).
#define ASTRIDE 36
#define BSTRIDE 136
#define ASZ (128 * ASTRIDE)
#define BSZ (32 * BSTRIDE)
#define GEMM_SMEM ((ASZ + BSZ) * 2 * 4)

__global__ void __launch_bounds__(256, 2)
gemm_tc_k(const float* __restrict__ A,
          const uint32_t* __restrict__ W0, const float* __restrict__ b0, float* __restrict__ C0,
          const uint32_t* __restrict__ W1, const float* __restrict__ b1, float* __restrict__ C1,
          int M, int relu, int cvtA, int c0half) {
    const uint32_t* W  = blockIdx.y ? W1 : W0;
    const float* bias  = blockIdx.y ? b1 : b0;
    float*       Cm    = blockIdx.y ? C1 : C0;
    const int    fp16out = (blockIdx.y == 0) ? c0half : 0;

    extern __shared__ float sm[];
    float*    As[2] = { sm, sm + ASZ };
    uint32_t* Bs[2] = { (uint32_t*)(sm + 2 * ASZ), (uint32_t*)(sm + 2 * ASZ + BSZ) };

    const int t = threadIdx.x;
    const int lane = t & 31;
    const int wid = t >> 5;
    const int warp_m = wid & 3;
    const int warp_n = wid >> 2;
    const int row0 = blockIdx.x * 128;

    const int a_row = t >> 1;
    const int a_colb = (t & 1) * 16;
    const int b_k = t >> 3;
    const int b_nb = (t & 7) * 16;
    const bool a_ok = (row0 + a_row) < M;
    const float* Arow = A + (size_t)(row0 + a_row) * 128;

    float acc[2][8][4];
#pragma unroll
    for (int i = 0; i < 2; i++)
#pragma unroll
        for (int j = 0; j < 8; j++)
#pragma unroll
            for (int k = 0; k < 4; k++) acc[i][j][k] = 0.f;

#pragma unroll
    for (int q = 0; q < 4; q++) {
        cp16(&As[0][a_row * ASTRIDE + a_colb + q * 4], Arow + a_colb + q * 4, a_ok);
        cp16(&Bs[0][b_k * BSTRIDE + b_nb + q * 4], W + (size_t)b_k * 128 + b_nb + q * 4, true);
    }
    cp_commit();

    int buf = 0;
    for (int c = 0; c < 4; c++) {
        cp_wait();
        __syncthreads();
        if (c < 3) {
            int k0 = (c + 1) * 32;
            int nb = buf ^ 1;
#pragma unroll
            for (int q = 0; q < 4; q++) {
                cp16(&As[nb][a_row * ASTRIDE + a_colb + q * 4], Arow + k0 + a_colb + q * 4, a_ok);
                cp16(&Bs[nb][b_k * BSTRIDE + b_nb + q * 4], W + (size_t)(k0 + b_k) * 128 + b_nb + q * 4, true);
            }
            cp_commit();
        }
        const uint32_t* as = (const uint32_t*)As[buf];
        const uint32_t* bs = Bs[buf];
        const int ar = warp_m * 32 + (lane >> 2);
        const int ac = lane & 3;
        const int bn = warp_n * 64 + (lane >> 2);
        const int bk = lane & 3;
#pragma unroll
        for (int ks = 0; ks < 4; ks++) {
            uint32_t af[2][4];
#pragma unroll
            for (int mt = 0; mt < 2; mt++) {
                const uint32_t* ap = as + (ar + mt * 16) * ASTRIDE + ks * 8 + ac;
                uint32_t r0 = ap[0];
                uint32_t r1 = ap[8 * ASTRIDE];
                uint32_t r2 = ap[4];
                uint32_t r3 = ap[8 * ASTRIDE + 4];
                if (cvtA) {
                    r0 = to_tf32(__uint_as_float(r0));
                    r1 = to_tf32(__uint_as_float(r1));
                    r2 = to_tf32(__uint_as_float(r2));
                    r3 = to_tf32(__uint_as_float(r3));
                }
                af[mt][0] = r0; af[mt][1] = r1; af[mt][2] = r2; af[mt][3] = r3;
            }
#pragma unroll
            for (int nt = 0; nt < 8; nt++) {
                const uint32_t* bp = bs + (ks * 8 + bk) * BSTRIDE + bn + nt * 8;
                uint32_t bf0 = bp[0];
                uint32_t bf1 = bp[4 * BSTRIDE];
                mma_tf32(acc[0][nt], af[0][0], af[0][1], af[0][2], af[0][3], bf0, bf1);
                mma_tf32(acc[1][nt], af[1][0], af[1][1], af[1][2], af[1][3], bf0, bf1);
            }
        }
        __syncthreads();
        buf ^= 1;
    }

    const int crow = row0 + warp_m * 32 + (lane >> 2);
    const int ccol0 = warp_n * 64 + (lane & 3) * 2;     // even column
#pragma unroll
    for (int nt = 0; nt < 8; nt++) {
        int col = ccol0 + nt * 8;
        float bx = bias[col], by = bias[col + 1];
#pragma unroll
        for (int mt = 0; mt < 2; mt++) {
            int r0 = crow + mt * 16;
            float v0 = acc[mt][nt][0] + bx, v1 = acc[mt][nt][1] + by;
            float v2 = acc[mt][nt][2] + bx, v3 = acc[mt][nt][3] + by;
            if (relu) {
                v0 = fmaxf(v0, 0.f); v1 = fmaxf(v1, 0.f);
                v2 = fmaxf(v2, 0.f); v3 = fmaxf(v3, 0.f);
            }
            if (fp16out) {
                uint32_t* Ch = (uint32_t*)Cm;
                __half2 h0 = __floats2half2_rn(v0, v1);
                __half2 h1 = __floats2half2_rn(v2, v3);
                if (r0 < M)     Ch[(size_t)r0 * 64 + (col >> 1)]       = *(uint32_t*)&h0;
                if (r0 + 8 < M) Ch[(size_t)(r0 + 8) * 64 + (col >> 1)] = *(uint32_t*)&h1;
            } else {
                if (r0 < M)     *(float2*)(Cm + (size_t)r0 * 128 + col)       = make_float2(v0, v1);
                if (r0 + 8 < M) *(float2*)(Cm + (size_t)(r0 + 8) * 128 + col) = make_float2(v2, v3);
            }
        }
    }
}

// ================= per-node fused GAT layer (fp16 gather, dual-stream) ======
__global__ void __launch_bounds__(128)
node_agg_k(const float* __restrict__ We, const float* __restrict__ att,
           const float* __restrict__ bo) {
    int n = (blockIdx.x * blockDim.x + threadIdx.x) >> 5;
    int lane = threadIdx.x & 31;
    if (n >= Nn) return;

    float4 br  = *(const float4*)(g_xr + (size_t)n * 128 + lane * 4);
    float4 w4  = *(const float4*)(We + lane * 4);
    float4 at4 = *(const float4*)(att + lane * 4);

    float4 accA = make_float4(0.f, 0.f, 0.f, 0.f);
    float4 accB = make_float4(0.f, 0.f, 0.f, 0.f);
    float ssA = 0.f, ssB = 0.f;

    const int beg = g_beg[n];
    const int cnt = g_cnt[n];
    const int half = cnt >> 1;
    const int mid = beg + half;

    // self loop -> stream A
    {
        float4 a = ld_xl16(n, lane);
        float attr = g_lattr[n];
        float m0 = lrelu(a.x + br.x + attr * w4.x);
        float m1 = lrelu(a.y + br.y + attr * w4.y);
        float m2 = lrelu(a.z + br.z + attr * w4.z);
        float m3 = lrelu(a.w + br.w + attr * w4.w);
        float p = m0 * at4.x + m1 * at4.y + m2 * at4.z + m3 * at4.w;
        p += __shfl_xor_sync(0xFFFFFFFFu, p, 1);
        p += __shfl_xor_sync(0xFFFFFFFFu, p, 2);
        p += __shfl_xor_sync(0xFFFFFFFFu, p, 4);
        float e = __expf(p);
        accA.x = fmaf(e, a.x, accA.x);
        accA.y = fmaf(e, a.y, accA.y);
        accA.z = fmaf(e, a.z, accA.z);
        accA.w = fmaf(e, a.w, accA.w);
        ssA += e;
    }

    for (int k = 0; k < half; k++) {
        int2 edA = g_edge[beg + k];
        int2 edB = g_edge[mid + k];
        float4 aA = ld_xl16(edA.x, lane);
        float4 aB = ld_xl16(edB.x, lane);
        float atA = __int_as_float(edA.y);
        float atB = __int_as_float(edB.y);
        float pA, pB;
        {
            float m0 = lrelu(aA.x + br.x + atA * w4.x);
            float n0 = lrelu(aB.x + br.x + atB * w4.x);
            float m1 = lrelu(aA.y + br.y + atA * w4.y);
            float n1 = lrelu(aB.y + br.y + atB * w4.y);
            float m2 = lrelu(aA.z + br.z + atA * w4.z);
            float n2 = lrelu(aB.z + br.z + atB * w4.z);
            float m3 = lrelu(aA.w + br.w + atA * w4.w);
            float n3 = lrelu(aB.w + br.w + atB * w4.w);
            pA = m0 * at4.x + m1 * at4.y + m2 * at4.z + m3 * at4.w;
            pB = n0 * at4.x + n1 * at4.y + n2 * at4.z + n3 * at4.w;
        }
        pA += __shfl_xor_sync(0xFFFFFFFFu, pA, 1);
        pB += __shfl_xor_sync(0xFFFFFFFFu, pB, 1);
        pA += __shfl_xor_sync(0xFFFFFFFFu, pA, 2);
        pB += __shfl_xor_sync(0xFFFFFFFFu, pB, 2);
        pA += __shfl_xor_sync(0xFFFFFFFFu, pA, 4);
        pB += __shfl_xor_sync(0xFFFFFFFFu, pB, 4);
        float eA = __expf(pA);
        float eB = __expf(pB);
        accA.x = fmaf(eA, aA.x, accA.x);
        accB.x = fmaf(eB, aB.x, accB.x);
        accA.y = fmaf(eA, aA.y, accA.y);
        accB.y = fmaf(eB, aB.y, accB.y);
        accA.z = fmaf(eA, aA.z, accA.z);
        accB.z = fmaf(eB, aB.z, accB.z);
        accA.w = fmaf(eA, aA.w, accA.w);
        accB.w = fmaf(eB, aB.w, accB.w);
        ssA += eA;
        ssB += eB;
    }
    if (cnt & 1) {
        int2 ed = g_edge[beg + 2 * half];
        float attr = __int_as_float(ed.y);
        float4 a = ld_xl16(ed.x, lane);
        float m0 = lrelu(a.x + br.x + attr * w4.x);
        float m1 = lrelu(a.y + br.y + attr * w4.y);
        float m2 = lrelu(a.z + br.z + attr * w4.z);
        float m3 = lrelu(a.w + br.w + attr * w4.w);
        float p = m0 * at4.x + m1 * at4.y + m2 * at4.z + m3 * at4.w;
        p += __shfl_xor_sync(0xFFFFFFFFu, p, 1);
        p += __shfl_xor_sync(0xFFFFFFFFu, p, 2);
        p += __shfl_xor_sync(0xFFFFFFFFu, p, 4);
        float e = __expf(p);
        accB.x = fmaf(e, a.x, accB.x);
        accB.y = fmaf(e, a.y, accB.y);
        accB.z = fmaf(e, a.z, accB.z);
        accB.w = fmaf(e, a.w, accB.w);
        ssB += e;
    }

    float inv = 1.f / (ssA + ssB + 1e-16f);
    float4 bo4 = *(const float4*)(bo + lane * 4);
    uint4 o;
    o.x = to_tf32(fmaxf((accA.x + accB.x) * inv + bo4.x, 0.f));
    o.y = to_tf32(fmaxf((accA.y + accB.y) * inv + bo4.y, 0.f));
    o.z = to_tf32(fmaxf((accA.z + accB.z) * inv + bo4.z, 0.f));
    o.w = to_tf32(fmaxf((accA.w + accB.w) * inv + bo4.w, 0.f));
    *(uint4*)(g_h + (size_t)n * 128 + lane * 4) = o;
}

// ================= launch ===================================================
extern "C" void kernel_launch(void* const* d_in, const int* in_sizes, int n_in,
                              void* d_out, int out_size) {
    const float* x    = (const float*)d_in[0];
    const int*   ei   = (const int*)  d_in[1];
    const float* ea   = (const float*)d_in[2];
    const float* Wl1  = (const float*)d_in[3];
    const float* bl1  = (const float*)d_in[4];
    const float* Wr1  = (const float*)d_in[5];
    const float* br1  = (const float*)d_in[6];
    const float* We1  = (const float*)d_in[7];
    const float* att1 = (const float*)d_in[8];
    const float* bo1  = (const float*)d_in[9];
    const float* Wl2  = (const float*)d_in[10];
    const float* bl2  = (const float*)d_in[11];
    const float* Wr2  = (const float*)d_in[12];
    const float* br2  = (const float*)d_in[13];
    const float* We2  = (const float*)d_in[14];
    const float* att2 = (const float*)d_in[15];
    const float* bo2  = (const float*)d_in[16];
    const float* Wlin = (const float*)d_in[17];
    const float* blin = (const float*)d_in[18];
    float* out = (float*)d_out;

    float *pxl16, *pxr, *ph;
    uint32_t* pw;
    void *pcnt, *plsum;
    cudaGetSymbolAddress((void**)&pxl16, g_xl16);
    cudaGetSymbolAddress((void**)&pxr,   g_xr);
    cudaGetSymbolAddress((void**)&ph,    g_h);
    cudaGetSymbolAddress((void**)&pw,    g_wtf);
    cudaGetSymbolAddress(&pcnt,  g_cnt);
    cudaGetSymbolAddress(&plsum, g_lsum);

    static int smem_set = 0;
    if (!smem_set) {
        cudaFuncSetAttribute(gemm_tc_k, cudaFuncAttributeMaxDynamicSharedMemorySize, GEMM_SMEM);
        smem_set = 1;
    }

    const int TB = 256;
    const int gb_n  = (Nn + TB - 1) / TB;
    const int gb_e  = (Ee + TB - 1) / TB;
    const int gb_w  = (5 * 16384 + TB - 1) / TB;
    const int gb_gemm = (Nn + 127) / 128;
    const int gb_node = (Nn * 32 + 127) / 128;
    dim3 grid2(gb_gemm, 2), grid1(gb_gemm, 1);

    const uint32_t* wl1 = pw + 0 * 16384;
    const uint32_t* wr1 = pw + 1 * 16384;
    const uint32_t* wl2 = pw + 2 * 16384;
    const uint32_t* wr2 = pw + 3 * 16384;
    const uint32_t* wli = pw + 4 * 16384;

    // ---- CSR build (node-ordered) + weight preconvert ----
    cudaMemsetAsync(pcnt,  0, Nn * sizeof(int));
    cudaMemsetAsync(plsum, 0, Nn * sizeof(float));
    cvtW_k<<<gb_w, TB>>>(Wl1, Wr1, Wl2, Wr2, Wlin);
    hist_k<<<gb_e, TB>>>(ei, ea);
    scan1_k<<<NB_SCAN, 256>>>();
    scan2_k<<<1, 32>>>();
    scan3_k<<<gb_n, TB>>>();
    scatter_k<<<gb_e, TB>>>(ei, ea);

    // ---- layer 1 (A = raw x -> cvtA=1; xl stored fp16) ----
    gemm_tc_k<<<grid2, TB, GEMM_SMEM>>>(x, wl1, bl1, pxl16, wr1, br1, pxr, Nn, 0, 1, 1);
    node_agg_k<<<gb_node, 128>>>(We1, att1, bo1);

    // ---- layer 2 (A = pre-rounded h -> cvtA=0; xl stored fp16) ----
    gemm_tc_k<<<grid2, TB, GEMM_SMEM>>>(ph, wl2, bl2, pxl16, wr2, br2, pxr, Nn, 0, 0, 1);
    node_agg_k<<<gb_node, 128>>>(We2, att2, bo2);

    // ---- final linear + relu -> d_out (fp32 out) ----
    gemm_tc_k<<<grid1, TB, GEMM_SMEM>>>(ph, wli, blin, out, wli, blin, out, Nn, 1, 0, 0);
}

// round 9
// speedup vs baseline: 1.1181x; 1.0411x over previous
#include <cuda_runtime.h>
#include <cuda_fp16.h>
#include <cstdint>

#define Nn 50000
#define Ee 800000
#define NEG 0.2f
#define NB_SCAN ((Nn + 255) / 256)

// ---------------- scratch (device globals; no runtime allocation) ----------
__device__ uint32_t g_xl16[(size_t)Nn * 64];   // xl in half2 pairs (128 ch = 64 uints)
__device__ float    g_xr[(size_t)Nn * 128];
__device__ float    g_h[(size_t)Nn * 128];
__device__ float    g_lsum[Nn];
__device__ float    g_lattr[Nn];
__device__ int      g_cnt[Nn];
__device__ int      g_beg[Nn];
__device__ int      g_wp[Nn];
__device__ int      g_bsum[NB_SCAN];
__device__ int      g_boff[NB_SCAN];
__device__ int2     g_edge[Ee];                // (src, attr-bits)
__device__ uint32_t g_wtf[5 * 128 * 128];      // weights pre-converted to tf32 bits

// ---------------- helpers ---------------------------------------------------
__device__ __forceinline__ float lrelu(float v) { return (v > 0.f) ? v : NEG * v; }

__device__ __forceinline__ uint32_t to_tf32(float f) {
    uint32_t u;
    asm("cvt.rna.tf32.f32 %0, %1;" : "=r"(u) : "f"(f));
    return u;
}
__device__ __forceinline__ void cp16(void* s, const void* g, bool pred) {
    unsigned sa = (unsigned)__cvta_generic_to_shared(s);
    int sz = pred ? 16 : 0;
    asm volatile("cp.async.cg.shared.global [%0], [%1], 16, %2;\n"
                 :: "r"(sa), "l"(g), "r"(sz));
}
__device__ __forceinline__ void cp_commit() { asm volatile("cp.async.commit_group;\n"); }
__device__ __forceinline__ void cp_wait()   { asm volatile("cp.async.wait_group 0;\n"); }

__device__ __forceinline__ void mma_tf32(float c[4], uint32_t a0, uint32_t a1,
                                         uint32_t a2, uint32_t a3,
                                         uint32_t b0, uint32_t b1) {
    asm volatile(
        "mma.sync.aligned.m16n8k8.row.col.f32.tf32.tf32.f32 "
        "{%0,%1,%2,%3}, {%4,%5,%6,%7}, {%8,%9}, {%0,%1,%2,%3};\n"
        : "+f"(c[0]), "+f"(c[1]), "+f"(c[2]), "+f"(c[3])
        : "r"(a0), "r"(a1), "r"(a2), "r"(a3), "r"(b0), "r"(b1));
}
__device__ __forceinline__ float4 ld_xl16(int node, int lane) {
    uint2 u = *(const uint2*)(g_xl16 + (size_t)node * 64 + lane * 2);
    float2 lo = __half22float2(*(const __half2*)&u.x);
    float2 hi = __half22float2(*(const __half2*)&u.y);
    return make_float4(lo.x, lo.y, hi.x, hi.y);
}

// ================= weight preconvert (once per launch) ======================
__global__ void cvtW_k(const float* __restrict__ w0, const float* __restrict__ w1,
                       const float* __restrict__ w2, const float* __restrict__ w3,
                       const float* __restrict__ w4) {
    int i = blockIdx.x * blockDim.x + threadIdx.x;
    if (i >= 5 * 16384) return;
    int slot = i >> 14, off = i & 16383;
    const float* s = (slot == 0) ? w0 : (slot == 1) ? w1 : (slot == 2) ? w2
                   : (slot == 3) ? w3 : w4;
    g_wtf[i] = to_tf32(s[off]);
}

// ================= CSR build (deterministic node-ordered scan) ==============
__global__ void zero_k() {
    int i = blockIdx.x * blockDim.x + threadIdx.x;
    if (i < Nn) { g_cnt[i] = 0; g_lsum[i] = 0.f; }
}
__global__ void hist_k(const int* __restrict__ ei, const float* __restrict__ ea) {
    int e = blockIdx.x * blockDim.x + threadIdx.x;
    if (e < Ee) {
        int dst = ei[Ee + e];
        atomicAdd(&g_cnt[dst], 1);
        atomicAdd(&g_lsum[dst], ea[e]);
    }
}
__global__ void scan1_k() {
    __shared__ int s[256];
    int t = threadIdx.x;
    int i = blockIdx.x * 256 + t;
    int v = (i < Nn) ? g_cnt[i] : 0;
    s[t] = v; __syncthreads();
#pragma unroll
    for (int off = 1; off < 256; off <<= 1) {
        int add = (t >= off) ? s[t - off] : 0;
        __syncthreads();
        s[t] += add;
        __syncthreads();
    }
    if (i < Nn) g_beg[i] = s[t] - v;
    if (t == 255) g_bsum[blockIdx.x] = s[255];
}
__global__ void scan2_k() {
    int lane = threadIdx.x;
    int carry = 0;
    for (int base = 0; base < NB_SCAN; base += 32) {
        int i = base + lane;
        int v = (i < NB_SCAN) ? g_bsum[i] : 0;
        int s = v;
#pragma unroll
        for (int off = 1; off < 32; off <<= 1) {
            int u = __shfl_up_sync(0xFFFFFFFFu, s, off);
            if (lane >= off) s += u;
        }
        if (i < NB_SCAN) g_boff[i] = carry + s - v;
        carry += __shfl_sync(0xFFFFFFFFu, s, 31);
    }
}
__global__ void scan3_k() {
    int n = blockIdx.x * blockDim.x + threadIdx.x;
    if (n >= Nn) return;
    int beg = g_beg[n] + g_boff[n >> 8];
    g_beg[n] = beg;
    g_wp[n] = beg;
    int c = g_cnt[n];
    g_lattr[n] = (c > 0) ? g_lsum[n] / (float)c : 0.f;
}
__global__ void scatter_k(const int* __restrict__ ei, const float* __restrict__ ea) {
    int e = blockIdx.x * blockDim.x + threadIdx.x;
    if (e < Ee) {
        int dst = ei[Ee + e];
        int pos = atomicAdd(&g_wp[dst], 1);
        g_edge[pos] = make_int2(ei[e], __float_as_int(ea[e]));
    }
}

// ================= tf32 tensor-core GEMM ====================================
#define ASTRIDE 36
#define BSTRIDE 136
#define ASZ (128 * ASTRIDE)
#define BSZ (32 * BSTRIDE)
#define GEMM_SMEM ((ASZ + BSZ) * 2 * 4)

__global__ void __launch_bounds__(256, 2)
gemm_tc_k(const float* __restrict__ A,
          const uint32_t* __restrict__ W0, const float* __restrict__ b0, float* __restrict__ C0,
          const uint32_t* __restrict__ W1, const float* __restrict__ b1, float* __restrict__ C1,
          int M, int relu, int cvtA, int c0half) {
    const uint32_t* W  = blockIdx.y ? W1 : W0;
    const float* bias  = blockIdx.y ? b1 : b0;
    float*       Cm    = blockIdx.y ? C1 : C0;
    const int    fp16out = (blockIdx.y == 0) ? c0half : 0;

    extern __shared__ float sm[];
    float*    As[2] = { sm, sm + ASZ };
    uint32_t* Bs[2] = { (uint32_t*)(sm + 2 * ASZ), (uint32_t*)(sm + 2 * ASZ + BSZ) };

    const int t = threadIdx.x;
    const int lane = t & 31;
    const int wid = t >> 5;
    const int warp_m = wid & 3;
    const int warp_n = wid >> 2;
    const int row0 = blockIdx.x * 128;

    const int a_row = t >> 1;
    const int a_colb = (t & 1) * 16;
    const int b_k = t >> 3;
    const int b_nb = (t & 7) * 16;
    const bool a_ok = (row0 + a_row) < M;
    const float* Arow = A + (size_t)(row0 + a_row) * 128;

    float acc[2][8][4];
#pragma unroll
    for (int i = 0; i < 2; i++)
#pragma unroll
        for (int j = 0; j < 8; j++)
#pragma unroll
            for (int k = 0; k < 4; k++) acc[i][j][k] = 0.f;

#pragma unroll
    for (int q = 0; q < 4; q++) {
        cp16(&As[0][a_row * ASTRIDE + a_colb + q * 4], Arow + a_colb + q * 4, a_ok);
        cp16(&Bs[0][b_k * BSTRIDE + b_nb + q * 4], W + (size_t)b_k * 128 + b_nb + q * 4, true);
    }
    cp_commit();

    int buf = 0;
    for (int c = 0; c < 4; c++) {
        cp_wait();
        __syncthreads();
        if (c < 3) {
            int k0 = (c + 1) * 32;
            int nb = buf ^ 1;
#pragma unroll
            for (int q = 0; q < 4; q++) {
                cp16(&As[nb][a_row * ASTRIDE + a_colb + q * 4], Arow + k0 + a_colb + q * 4, a_ok);
                cp16(&Bs[nb][b_k * BSTRIDE + b_nb + q * 4], W + (size_t)(k0 + b_k) * 128 + b_nb + q * 4, true);
            }
            cp_commit();
        }
        const uint32_t* as = (const uint32_t*)As[buf];
        const uint32_t* bs = Bs[buf];
        const int ar = warp_m * 32 + (lane >> 2);
        const int ac = lane & 3;
        const int bn = warp_n * 64 + (lane >> 2);
        const int bk = lane & 3;
#pragma unroll
        for (int ks = 0; ks < 4; ks++) {
            uint32_t af[2][4];
#pragma unroll
            for (int mt = 0; mt < 2; mt++) {
                const uint32_t* ap = as + (ar + mt * 16) * ASTRIDE + ks * 8 + ac;
                uint32_t r0 = ap[0];
                uint32_t r1 = ap[8 * ASTRIDE];
                uint32_t r2 = ap[4];
                uint32_t r3 = ap[8 * ASTRIDE + 4];
                if (cvtA) {
                    r0 = to_tf32(__uint_as_float(r0));
                    r1 = to_tf32(__uint_as_float(r1));
                    r2 = to_tf32(__uint_as_float(r2));
                    r3 = to_tf32(__uint_as_float(r3));
                }
                af[mt][0] = r0; af[mt][1] = r1; af[mt][2] = r2; af[mt][3] = r3;
            }
#pragma unroll
            for (int nt = 0; nt < 8; nt++) {
                const uint32_t* bp = bs + (ks * 8 + bk) * BSTRIDE + bn + nt * 8;
                uint32_t bf0 = bp[0];
                uint32_t bf1 = bp[4 * BSTRIDE];
                mma_tf32(acc[0][nt], af[0][0], af[0][1], af[0][2], af[0][3], bf0, bf1);
                mma_tf32(acc[1][nt], af[1][0], af[1][1], af[1][2], af[1][3], bf0, bf1);
            }
        }
        __syncthreads();
        buf ^= 1;
    }

    const int crow = row0 + warp_m * 32 + (lane >> 2);
    const int ccol0 = warp_n * 64 + (lane & 3) * 2;
#pragma unroll
    for (int nt = 0; nt < 8; nt++) {
        int col = ccol0 + nt * 8;
        float bx = bias[col], by = bias[col + 1];
#pragma unroll
        for (int mt = 0; mt < 2; mt++) {
            int r0 = crow + mt * 16;
            float v0 = acc[mt][nt][0] + bx, v1 = acc[mt][nt][1] + by;
            float v2 = acc[mt][nt][2] + bx, v3 = acc[mt][nt][3] + by;
            if (relu) {
                v0 = fmaxf(v0, 0.f); v1 = fmaxf(v1, 0.f);
                v2 = fmaxf(v2, 0.f); v3 = fmaxf(v3, 0.f);
            }
            if (fp16out) {
                uint32_t* Ch = (uint32_t*)Cm;
                __half2 h0 = __floats2half2_rn(v0, v1);
                __half2 h1 = __floats2half2_rn(v2, v3);
                if (r0 < M)     Ch[(size_t)r0 * 64 + (col >> 1)]       = *(uint32_t*)&h0;
                if (r0 + 8 < M) Ch[(size_t)(r0 + 8) * 64 + (col >> 1)] = *(uint32_t*)&h1;
            } else {
                if (r0 < M)     *(float2*)(Cm + (size_t)r0 * 128 + col)       = make_float2(v0, v1);
                if (r0 + 8 < M) *(float2*)(Cm + (size_t)(r0 + 8) * 128 + col) = make_float2(v2, v3);
            }
        }
    }
}

// ================= per-node fused GAT layer (fp16 gather, dual-stream) ======
__global__ void __launch_bounds__(128)
node_agg_k(const float* __restrict__ We, const float* __restrict__ att,
           const float* __restrict__ bo) {
    int n = (blockIdx.x * blockDim.x + threadIdx.x) >> 5;
    int lane = threadIdx.x & 31;
    if (n >= Nn) return;

    float4 br  = *(const float4*)(g_xr + (size_t)n * 128 + lane * 4);
    float4 w4  = *(const float4*)(We + lane * 4);
    float4 at4 = *(const float4*)(att + lane * 4);

    float4 accA = make_float4(0.f, 0.f, 0.f, 0.f);
    float4 accB = make_float4(0.f, 0.f, 0.f, 0.f);
    float ssA = 0.f, ssB = 0.f;

    const int beg = g_beg[n];
    const int cnt = g_cnt[n];
    const int half = cnt >> 1;
    const int mid = beg + half;

    // self loop -> stream A
    {
        float4 a = ld_xl16(n, lane);
        float attr = g_lattr[n];
        float m0 = lrelu(a.x + br.x + attr * w4.x);
        float m1 = lrelu(a.y + br.y + attr * w4.y);
        float m2 = lrelu(a.z + br.z + attr * w4.z);
        float m3 = lrelu(a.w + br.w + attr * w4.w);
        float p = m0 * at4.x + m1 * at4.y + m2 * at4.z + m3 * at4.w;
        p += __shfl_xor_sync(0xFFFFFFFFu, p, 1);
        p += __shfl_xor_sync(0xFFFFFFFFu, p, 2);
        p += __shfl_xor_sync(0xFFFFFFFFu, p, 4);
        float e = __expf(p);
        accA.x = fmaf(e, a.x, accA.x);
        accA.y = fmaf(e, a.y, accA.y);
        accA.z = fmaf(e, a.z, accA.z);
        accA.w = fmaf(e, a.w, accA.w);
        ssA += e;
    }

    for (int k = 0; k < half; k++) {
        int2 edA = g_edge[beg + k];
        int2 edB = g_edge[mid + k];
        float4 aA = ld_xl16(edA.x, lane);
        float4 aB = ld_xl16(edB.x, lane);
        float atA = __int_as_float(edA.y);
        float atB = __int_as_float(edB.y);
        float pA, pB;
        {
            float m0 = lrelu(aA.x + br.x + atA * w4.x);
            float n0 = lrelu(aB.x + br.x + atB * w4.x);
            float m1 = lrelu(aA.y + br.y + atA * w4.y);
            float n1 = lrelu(aB.y + br.y + atB * w4.y);
            float m2 = lrelu(aA.z + br.z + atA * w4.z);
            float n2 = lrelu(aB.z + br.z + atB * w4.z);
            float m3 = lrelu(aA.w + br.w + atA * w4.w);
            float n3 = lrelu(aB.w + br.w + atB * w4.w);
            pA = m0 * at4.x + m1 * at4.y + m2 * at4.z + m3 * at4.w;
            pB = n0 * at4.x + n1 * at4.y + n2 * at4.z + n3 * at4.w;
        }
        pA += __shfl_xor_sync(0xFFFFFFFFu, pA, 1);
        pB += __shfl_xor_sync(0xFFFFFFFFu, pB, 1);
        pA += __shfl_xor_sync(0xFFFFFFFFu, pA, 2);
        pB += __shfl_xor_sync(0xFFFFFFFFu, pB, 2);
        pA += __shfl_xor_sync(0xFFFFFFFFu, pA, 4);
        pB += __shfl_xor_sync(0xFFFFFFFFu, pB, 4);
        float eA = __expf(pA);
        float eB = __expf(pB);
        accA.x = fmaf(eA, aA.x, accA.x);
        accB.x = fmaf(eB, aB.x, accB.x);
        accA.y = fmaf(eA, aA.y, accA.y);
        accB.y = fmaf(eB, aB.y, accB.y);
        accA.z = fmaf(eA, aA.z, accA.z);
        accB.z = fmaf(eB, aB.z, accB.z);
        accA.w = fmaf(eA, aA.w, accA.w);
        accB.w = fmaf(eB, aB.w, accB.w);
        ssA += eA;
        ssB += eB;
    }
    if (cnt & 1) {
        int2 ed = g_edge[beg + 2 * half];
        float attr = __int_as_float(ed.y);
        float4 a = ld_xl16(ed.x, lane);
        float m0 = lrelu(a.x + br.x + attr * w4.x);
        float m1 = lrelu(a.y + br.y + attr * w4.y);
        float m2 = lrelu(a.z + br.z + attr * w4.z);
        float m3 = lrelu(a.w + br.w + attr * w4.w);
        float p = m0 * at4.x + m1 * at4.y + m2 * at4.z + m3 * at4.w;
        p += __shfl_xor_sync(0xFFFFFFFFu, p, 1);
        p += __shfl_xor_sync(0xFFFFFFFFu, p, 2);
        p += __shfl_xor_sync(0xFFFFFFFFu, p, 4);
        float e = __expf(p);
        accB.x = fmaf(e, a.x, accB.x);
        accB.y = fmaf(e, a.y, accB.y);
        accB.z = fmaf(e, a.z, accB.z);
        accB.w = fmaf(e, a.w, accB.w);
        ssB += e;
    }

    float inv = 1.f / (ssA + ssB + 1e-16f);
    float4 bo4 = *(const float4*)(bo + lane * 4);
    uint4 o;
    o.x = to_tf32(fmaxf((accA.x + accB.x) * inv + bo4.x, 0.f));
    o.y = to_tf32(fmaxf((accA.y + accB.y) * inv + bo4.y, 0.f));
    o.z = to_tf32(fmaxf((accA.z + accB.z) * inv + bo4.z, 0.f));
    o.w = to_tf32(fmaxf((accA.w + accB.w) * inv + bo4.w, 0.f));
    *(uint4*)(g_h + (size_t)n * 128 + lane * 4) = o;
}

// ================= launch ===================================================
extern "C" void kernel_launch(void* const* d_in, const int* in_sizes, int n_in,
                              void* d_out, int out_size) {
    const float* x    = (const float*)d_in[0];
    const int*   ei   = (const int*)  d_in[1];
    const float* ea   = (const float*)d_in[2];
    const float* Wl1  = (const float*)d_in[3];
    const float* bl1  = (const float*)d_in[4];
    const float* Wr1  = (const float*)d_in[5];
    const float* br1  = (const float*)d_in[6];
    const float* We1  = (const float*)d_in[7];
    const float* att1 = (const float*)d_in[8];
    const float* bo1  = (const float*)d_in[9];
    const float* Wl2  = (const float*)d_in[10];
    const float* bl2  = (const float*)d_in[11];
    const float* Wr2  = (const float*)d_in[12];
    const float* br2  = (const float*)d_in[13];
    const float* We2  = (const float*)d_in[14];
    const float* att2 = (const float*)d_in[15];
    const float* bo2  = (const float*)d_in[16];
    const float* Wlin = (const float*)d_in[17];
    const float* blin = (const float*)d_in[18];
    float* out = (float*)d_out;

    float *pxl16, *pxr, *ph;
    uint32_t* pw;
    cudaGetSymbolAddress((void**)&pxl16, g_xl16);
    cudaGetSymbolAddress((void**)&pxr,   g_xr);
    cudaGetSymbolAddress((void**)&ph,    g_h);
    cudaGetSymbolAddress((void**)&pw,    g_wtf);

    static cudaStream_t s1;
    static cudaEvent_t evFork, evCSR;
    static int inited = 0;
    if (!inited) {
        cudaFuncSetAttribute(gemm_tc_k, cudaFuncAttributeMaxDynamicSharedMemorySize, GEMM_SMEM);
        cudaStreamCreateWithFlags(&s1, cudaStreamNonBlocking);
        cudaEventCreateWithFlags(&evFork, cudaEventDisableTiming);
        cudaEventCreateWithFlags(&evCSR, cudaEventDisableTiming);
        inited = 1;
    }

    const int TB = 256;
    const int gb_n  = (Nn + TB - 1) / TB;
    const int gb_e  = (Ee + TB - 1) / TB;
    const int gb_w  = (5 * 16384 + TB - 1) / TB;
    const int gb_gemm = (Nn + 127) / 128;
    const int gb_node = (Nn * 32 + 127) / 128;
    dim3 grid2(gb_gemm, 2), grid1(gb_gemm, 1);

    const uint32_t* wl1 = pw + 0 * 16384;
    const uint32_t* wr1 = pw + 1 * 16384;
    const uint32_t* wl2 = pw + 2 * 16384;
    const uint32_t* wr2 = pw + 3 * 16384;
    const uint32_t* wli = pw + 4 * 16384;

    // ---- fork: CSR chain on s1, concurrent with cvtW+GEMM1 on s0 ----
    cudaEventRecord(evFork, 0);
    cudaStreamWaitEvent(s1, evFork, 0);

    zero_k<<<gb_n, TB, 0, s1>>>();
    hist_k<<<gb_e, TB, 0, s1>>>(ei, ea);
    scan1_k<<<NB_SCAN, 256, 0, s1>>>();
    scan2_k<<<1, 32, 0, s1>>>();
    scan3_k<<<gb_n, TB, 0, s1>>>();
    scatter_k<<<gb_e, TB, 0, s1>>>(ei, ea);
    cudaEventRecord(evCSR, s1);

    // s0: weight preconvert + layer-1 GEMMs (independent of CSR)
    cvtW_k<<<gb_w, TB>>>(Wl1, Wr1, Wl2, Wr2, Wlin);
    gemm_tc_k<<<grid2, TB, GEMM_SMEM>>>(x, wl1, bl1, pxl16, wr1, br1, pxr, Nn, 0, 1, 1);

    // join: node_agg needs both GEMM1 outputs and the CSR
    cudaStreamWaitEvent(0, evCSR, 0);
    node_agg_k<<<gb_node, 128>>>(We1, att1, bo1);

    // ---- layer 2 ----
    gemm_tc_k<<<grid2, TB, GEMM_SMEM>>>(ph, wl2, bl2, pxl16, wr2, br2, pxr, Nn, 0, 0, 1);
    node_agg_k<<<gb_node, 128>>>(We2, att2, bo2);

    // ---- final linear + relu -> d_out (fp32 out) ----
    gemm_tc_k<<<grid1, TB, GEMM_SMEM>>>(ph, wli, blin, out, wli, blin, out, Nn, 1, 0, 0);
}

// round 10
// speedup vs baseline: 1.1894x; 1.0638x over previous
#include <cuda_runtime.h>
#include <cuda_fp16.h>
#include <cstdint>

#define Nn 50000
#define Ee 800000
#define NEG 0.2f
#define NB_SCAN ((Nn + 255) / 256)

// ---------------- scratch (device globals; no runtime allocation) ----------
__device__ uint32_t g_xl16[(size_t)Nn * 64];   // xl in half2 pairs
__device__ uint32_t g_xr16[(size_t)Nn * 64];   // xr in half2 pairs
__device__ float    g_h[(size_t)Nn * 128];
__device__ float    g_lsum[Nn];
__device__ float    g_lattr[Nn];
__device__ int      g_cnt[Nn];
__device__ int      g_beg[Nn];
__device__ int      g_wp[Nn];
__device__ volatile unsigned g_scanstate[NB_SCAN];
__device__ int2     g_edge[Ee];                // (src, attr-bits)
__device__ uint32_t g_wtf[5 * 128 * 128];      // weights pre-converted to tf32 bits

#define AGG_READY    0x40000000u
#define PREFIX_READY 0x80000000u
#define VAL_MASK     0x3FFFFFFFu

// ---------------- helpers ---------------------------------------------------
__device__ __forceinline__ uint32_t to_tf32(float f) {
    uint32_t u;
    asm("cvt.rna.tf32.f32 %0, %1;" : "=r"(u) : "f"(f));
    return u;
}
__device__ __forceinline__ void cp16(void* s, const void* g, bool pred) {
    unsigned sa = (unsigned)__cvta_generic_to_shared(s);
    int sz = pred ? 16 : 0;
    asm volatile("cp.async.cg.shared.global [%0], [%1], 16, %2;\n"
                 :: "r"(sa), "l"(g), "r"(sz));
}
__device__ __forceinline__ void cp_commit() { asm volatile("cp.async.commit_group;\n"); }
__device__ __forceinline__ void cp_wait()   { asm volatile("cp.async.wait_group 0;\n"); }

__device__ __forceinline__ void mma_tf32(float c[4], uint32_t a0, uint32_t a1,
                                         uint32_t a2, uint32_t a3,
                                         uint32_t b0, uint32_t b1) {
    asm volatile(
        "mma.sync.aligned.m16n8k8.row.col.f32.tf32.tf32.f32 "
        "{%0,%1,%2,%3}, {%4,%5,%6,%7}, {%8,%9}, {%0,%1,%2,%3};\n"
        : "+f"(c[0]), "+f"(c[1]), "+f"(c[2]), "+f"(c[3])
        : "r"(a0), "r"(a1), "r"(a2), "r"(a3), "r"(b0), "r"(b1));
}
__device__ __forceinline__ __half2 lrelu2(__half2 v) {
    const __half2 z = __float2half2_rn(0.f);
    const __half2 c = __float2half2_rn(NEG);
    return __hfma2(c, __hmin2(v, z), __hmax2(v, z));
}

// ================= weight preconvert (once per launch) ======================
__global__ void cvtW_k(const float* __restrict__ w0, const float* __restrict__ w1,
                       const float* __restrict__ w2, const float* __restrict__ w3,
                       const float* __restrict__ w4) {
    int i = blockIdx.x * blockDim.x + threadIdx.x;
    if (i >= 5 * 16384) return;
    int slot = i >> 14, off = i & 16383;
    const float* s = (slot == 0) ? w0 : (slot == 1) ? w1 : (slot == 2) ? w2
                   : (slot == 3) ? w3 : w4;
    g_wtf[i] = to_tf32(s[off]);
}

// ================= CSR build ================================================
__global__ void zero_k() {
    int i = blockIdx.x * blockDim.x + threadIdx.x;
    if (i < Nn) { g_cnt[i] = 0; g_lsum[i] = 0.f; }
    if (i < NB_SCAN) g_scanstate[i] = 0u;
}
__global__ void hist_k(const int* __restrict__ ei, const float* __restrict__ ea) {
    int e = blockIdx.x * blockDim.x + threadIdx.x;
    if (e < Ee) {
        int dst = ei[Ee + e];
        atomicAdd(&g_cnt[dst], 1);
        atomicAdd(&g_lsum[dst], ea[e]);
    }
}
// single-pass decoupled-lookback scan + rowptr/lattr finalize
__global__ void scan_k() {
    __shared__ int s[256];
    __shared__ int s_prefix;
    const int b = blockIdx.x, t = threadIdx.x;
    const int i = b * 256 + t;
    int v = (i < Nn) ? g_cnt[i] : 0;
    s[t] = v; __syncthreads();
#pragma unroll
    for (int off = 1; off < 256; off <<= 1) {
        int add = (t >= off) ? s[t - off] : 0;
        __syncthreads();
        s[t] += add;
        __syncthreads();
    }
    const int total = s[255];
    if (t == 0) {
        if (b == 0) {
            g_scanstate[0] = (unsigned)total | PREFIX_READY;
            s_prefix = 0;
        } else {
            g_scanstate[b] = (unsigned)total | AGG_READY;
            int exc = 0;
            int j = b - 1;
            while (j >= 0) {
                unsigned st = g_scanstate[j];
                if (st & PREFIX_READY) { exc += (int)(st & VAL_MASK); break; }
                if (st & AGG_READY)    { exc += (int)(st & VAL_MASK); j--; }
                // else: spin until published
            }
            g_scanstate[b] = (unsigned)(exc + total) | PREFIX_READY;
            s_prefix = exc;
        }
    }
    __syncthreads();
    if (i < Nn) {
        int beg = s_prefix + s[t] - v;
        g_beg[i] = beg;
        g_wp[i] = beg;
        g_lattr[i] = (v > 0) ? g_lsum[i] / (float)v : 0.f;
    }
}
__global__ void scatter_k(const int* __restrict__ ei, const float* __restrict__ ea) {
    int e = blockIdx.x * blockDim.x + threadIdx.x;
    if (e < Ee) {
        int dst = ei[Ee + e];
        int pos = atomicAdd(&g_wp[dst], 1);
        g_edge[pos] = make_int2(ei[e], __float_as_int(ea[e]));
    }
}

// ================= tf32 tensor-core GEMM ====================================
#define ASTRIDE 36
#define BSTRIDE 136
#define ASZ (128 * ASTRIDE)
#define BSZ (32 * BSTRIDE)
#define GEMM_SMEM ((ASZ + BSZ) * 2 * 4)

__global__ void __launch_bounds__(256, 2)
gemm_tc_k(const float* __restrict__ A,
          const uint32_t* __restrict__ W0, const float* __restrict__ b0, float* __restrict__ C0,
          const uint32_t* __restrict__ W1, const float* __restrict__ b1, float* __restrict__ C1,
          int M, int relu, int cvtA, int halfout) {
    const uint32_t* W  = blockIdx.y ? W1 : W0;
    const float* bias  = blockIdx.y ? b1 : b0;
    float*       Cm    = blockIdx.y ? C1 : C0;

    extern __shared__ float sm[];
    float*    As[2] = { sm, sm + ASZ };
    uint32_t* Bs[2] = { (uint32_t*)(sm + 2 * ASZ), (uint32_t*)(sm + 2 * ASZ + BSZ) };

    const int t = threadIdx.x;
    const int lane = t & 31;
    const int wid = t >> 5;
    const int warp_m = wid & 3;
    const int warp_n = wid >> 2;
    const int row0 = blockIdx.x * 128;

    const int a_row = t >> 1;
    const int a_colb = (t & 1) * 16;
    const int b_k = t >> 3;
    const int b_nb = (t & 7) * 16;
    const bool a_ok = (row0 + a_row) < M;
    const float* Arow = A + (size_t)(row0 + a_row) * 128;

    float acc[2][8][4];
#pragma unroll
    for (int i = 0; i < 2; i++)
#pragma unroll
        for (int j = 0; j < 8; j++)
#pragma unroll
            for (int k = 0; k < 4; k++) acc[i][j][k] = 0.f;

#pragma unroll
    for (int q = 0; q < 4; q++) {
        cp16(&As[0][a_row * ASTRIDE + a_colb + q * 4], Arow + a_colb + q * 4, a_ok);
        cp16(&Bs[0][b_k * BSTRIDE + b_nb + q * 4], W + (size_t)b_k * 128 + b_nb + q * 4, true);
    }
    cp_commit();

    int buf = 0;
    for (int c = 0; c < 4; c++) {
        cp_wait();
        __syncthreads();
        if (c < 3) {
            int k0 = (c + 1) * 32;
            int nb = buf ^ 1;
#pragma unroll
            for (int q = 0; q < 4; q++) {
                cp16(&As[nb][a_row * ASTRIDE + a_colb + q * 4], Arow + k0 + a_colb + q * 4, a_ok);
                cp16(&Bs[nb][b_k * BSTRIDE + b_nb + q * 4], W + (size_t)(k0 + b_k) * 128 + b_nb + q * 4, true);
            }
            cp_commit();
        }
        const uint32_t* as = (const uint32_t*)As[buf];
        const uint32_t* bs = Bs[buf];
        const int ar = warp_m * 32 + (lane >> 2);
        const int ac = lane & 3;
        const int bn = warp_n * 64 + (lane >> 2);
        const int bk = lane & 3;
#pragma unroll
        for (int ks = 0; ks < 4; ks++) {
            uint32_t af[2][4];
#pragma unroll
            for (int mt = 0; mt < 2; mt++) {
                const uint32_t* ap = as + (ar + mt * 16) * ASTRIDE + ks * 8 + ac;
                uint32_t r0 = ap[0];
                uint32_t r1 = ap[8 * ASTRIDE];
                uint32_t r2 = ap[4];
                uint32_t r3 = ap[8 * ASTRIDE + 4];
                if (cvtA) {
                    r0 = to_tf32(__uint_as_float(r0));
                    r1 = to_tf32(__uint_as_float(r1));
                    r2 = to_tf32(__uint_as_float(r2));
                    r3 = to_tf32(__uint_as_float(r3));
                }
                af[mt][0] = r0; af[mt][1] = r1; af[mt][2] = r2; af[mt][3] = r3;
            }
#pragma unroll
            for (int nt = 0; nt < 8; nt++) {
                const uint32_t* bp = bs + (ks * 8 + bk) * BSTRIDE + bn + nt * 8;
                uint32_t bf0 = bp[0];
                uint32_t bf1 = bp[4 * BSTRIDE];
                mma_tf32(acc[0][nt], af[0][0], af[0][1], af[0][2], af[0][3], bf0, bf1);
                mma_tf32(acc[1][nt], af[1][0], af[1][1], af[1][2], af[1][3], bf0, bf1);
            }
        }
        __syncthreads();
        buf ^= 1;
    }

    const int crow = row0 + warp_m * 32 + (lane >> 2);
    const int ccol0 = warp_n * 64 + (lane & 3) * 2;
#pragma unroll
    for (int nt = 0; nt < 8; nt++) {
        int col = ccol0 + nt * 8;
        float bx = bias[col], by = bias[col + 1];
#pragma unroll
        for (int mt = 0; mt < 2; mt++) {
            int r0 = crow + mt * 16;
            float v0 = acc[mt][nt][0] + bx, v1 = acc[mt][nt][1] + by;
            float v2 = acc[mt][nt][2] + bx, v3 = acc[mt][nt][3] + by;
            if (relu) {
                v0 = fmaxf(v0, 0.f); v1 = fmaxf(v1, 0.f);
                v2 = fmaxf(v2, 0.f); v3 = fmaxf(v3, 0.f);
            }
            if (halfout) {
                uint32_t* Ch = (uint32_t*)Cm;
                __half2 h0 = __floats2half2_rn(v0, v1);
                __half2 h1 = __floats2half2_rn(v2, v3);
                if (r0 < M)     Ch[(size_t)r0 * 64 + (col >> 1)]       = *(uint32_t*)&h0;
                if (r0 + 8 < M) Ch[(size_t)(r0 + 8) * 64 + (col >> 1)] = *(uint32_t*)&h1;
            } else {
                if (r0 < M)     *(float2*)(Cm + (size_t)r0 * 128 + col)       = make_float2(v0, v1);
                if (r0 + 8 < M) *(float2*)(Cm + (size_t)(r0 + 8) * 128 + col) = make_float2(v2, v3);
            }
        }
    }
}

// ================= per-node fused GAT layer (half2 math) ====================
__global__ void __launch_bounds__(128)
node_agg_k(const float* __restrict__ We, const float* __restrict__ att,
           const float* __restrict__ bo) {
    int n = (blockIdx.x * blockDim.x + threadIdx.x) >> 5;
    int lane = threadIdx.x & 31;
    if (n >= Nn) return;

    // per-lane constants in half2
    float4 wf = *(const float4*)(We + lane * 4);
    float4 tf = *(const float4*)(att + lane * 4);
    const __half2 w0 = __floats2half2_rn(wf.x, wf.y);
    const __half2 w1 = __floats2half2_rn(wf.z, wf.w);
    const __half2 t0 = __floats2half2_rn(tf.x, tf.y);
    const __half2 t1 = __floats2half2_rn(tf.z, tf.w);

    uint2 ub = *(const uint2*)(g_xr16 + (size_t)n * 64 + lane * 2);
    const __half2 b0 = *(const __half2*)&ub.x;
    const __half2 b1 = *(const __half2*)&ub.y;

    float4 acc = make_float4(0.f, 0.f, 0.f, 0.f);
    float ss = 0.f;

    const int beg = g_beg[n];
    const int end = beg + g_cnt[n];

    // process one edge (src, attr); updates acc/ss
    auto process = [&](int src, float attr) {
        uint2 ua = *(const uint2*)(g_xl16 + (size_t)src * 64 + lane * 2);
        __half2 a0 = *(const __half2*)&ua.x;
        __half2 a1 = *(const __half2*)&ua.y;
        __half2 at2 = __float2half2_rn(attr);
        __half2 v0 = __hfma2(at2, w0, __hadd2(a0, b0));
        __half2 v1 = __hfma2(at2, w1, __hadd2(a1, b1));
        __half2 m0 = lrelu2(v0);
        __half2 m1 = lrelu2(v1);
        __half2 p2 = __hfma2(m1, t1, __hmul2(m0, t0));
        float2 pf = __half22float2(p2);
        float p = pf.x + pf.y;
        p += __shfl_xor_sync(0xFFFFFFFFu, p, 1);
        p += __shfl_xor_sync(0xFFFFFFFFu, p, 2);
        p += __shfl_xor_sync(0xFFFFFFFFu, p, 4);
        float e = __expf(p);
        float2 f0 = __half22float2(a0);
        float2 f1 = __half22float2(a1);
        acc.x = fmaf(e, f0.x, acc.x);
        acc.y = fmaf(e, f0.y, acc.y);
        acc.z = fmaf(e, f1.x, acc.z);
        acc.w = fmaf(e, f1.y, acc.w);
        ss += e;
    };

    process(n, g_lattr[n]);          // self loop
    for (int j = beg; j < end; j++) {
        int2 ed = g_edge[j];
        process(ed.x, __int_as_float(ed.y));
    }

    float inv = 1.f / (ss + 1e-16f);
    float4 bo4 = *(const float4*)(bo + lane * 4);
    uint4 o;
    o.x = to_tf32(fmaxf(acc.x * inv + bo4.x, 0.f));
    o.y = to_tf32(fmaxf(acc.y * inv + bo4.y, 0.f));
    o.z = to_tf32(fmaxf(acc.z * inv + bo4.z, 0.f));
    o.w = to_tf32(fmaxf(acc.w * inv + bo4.w, 0.f));
    *(uint4*)(g_h + (size_t)n * 128 + lane * 4) = o;
}

// ================= launch ===================================================
extern "C" void kernel_launch(void* const* d_in, const int* in_sizes, int n_in,
                              void* d_out, int out_size) {
    const float* x    = (const float*)d_in[0];
    const int*   ei   = (const int*)  d_in[1];
    const float* ea   = (const float*)d_in[2];
    const float* Wl1  = (const float*)d_in[3];
    const float* bl1  = (const float*)d_in[4];
    const float* Wr1  = (const float*)d_in[5];
    const float* br1  = (const float*)d_in[6];
    const float* We1  = (const float*)d_in[7];
    const float* att1 = (const float*)d_in[8];
    const float* bo1  = (const float*)d_in[9];
    const float* Wl2  = (const float*)d_in[10];
    const float* bl2  = (const float*)d_in[11];
    const float* Wr2  = (const float*)d_in[12];
    const float* br2  = (const float*)d_in[13];
    const float* We2  = (const float*)d_in[14];
    const float* att2 = (const float*)d_in[15];
    const float* bo2  = (const float*)d_in[16];
    const float* Wlin = (const float*)d_in[17];
    const float* blin = (const float*)d_in[18];
    float* out = (float*)d_out;

    float *pxl16, *pxr16, *ph;
    uint32_t* pw;
    cudaGetSymbolAddress((void**)&pxl16, g_xl16);
    cudaGetSymbolAddress((void**)&pxr16, g_xr16);
    cudaGetSymbolAddress((void**)&ph,    g_h);
    cudaGetSymbolAddress((void**)&pw,    g_wtf);

    static cudaStream_t s1;
    static cudaEvent_t evFork, evCSR;
    static int inited = 0;
    if (!inited) {
        cudaFuncSetAttribute(gemm_tc_k, cudaFuncAttributeMaxDynamicSharedMemorySize, GEMM_SMEM);
        cudaStreamCreateWithFlags(&s1, cudaStreamNonBlocking);
        cudaEventCreateWithFlags(&evFork, cudaEventDisableTiming);
        cudaEventCreateWithFlags(&evCSR, cudaEventDisableTiming);
        inited = 1;
    }

    const int TB = 256;
    const int gb_n  = (Nn + TB - 1) / TB;
    const int gb_e  = (Ee + TB - 1) / TB;
    const int gb_w  = (5 * 16384 + TB - 1) / TB;
    const int gb_gemm = (Nn + 127) / 128;
    const int gb_node = (Nn * 32 + 127) / 128;
    dim3 grid2(gb_gemm, 2), grid1(gb_gemm, 1);

    const uint32_t* wl1 = pw + 0 * 16384;
    const uint32_t* wr1 = pw + 1 * 16384;
    const uint32_t* wl2 = pw + 2 * 16384;
    const uint32_t* wr2 = pw + 3 * 16384;
    const uint32_t* wli = pw + 4 * 16384;

    // ---- fork: CSR chain on s1, concurrent with cvtW+GEMM1 on s0 ----
    cudaEventRecord(evFork, 0);
    cudaStreamWaitEvent(s1, evFork, 0);

    zero_k<<<gb_n, TB, 0, s1>>>();
    hist_k<<<gb_e, TB, 0, s1>>>(ei, ea);
    scan_k<<<NB_SCAN, 256, 0, s1>>>();
    scatter_k<<<gb_e, TB, 0, s1>>>(ei, ea);
    cudaEventRecord(evCSR, s1);

    // s0: weight preconvert + layer-1 GEMMs
    cvtW_k<<<gb_w, TB>>>(Wl1, Wr1, Wl2, Wr2, Wlin);
    gemm_tc_k<<<grid2, TB, GEMM_SMEM>>>(x, wl1, bl1, pxl16, wr1, br1, pxr16, Nn, 0, 1, 1);

    // join: node_agg needs both GEMM1 outputs and the CSR
    cudaStreamWaitEvent(0, evCSR, 0);
    node_agg_k<<<gb_node, 128>>>(We1, att1, bo1);

    // ---- layer 2 ----
    gemm_tc_k<<<grid2, TB, GEMM_SMEM>>>(ph, wl2, bl2, pxl16, wr2, br2, pxr16, Nn, 0, 0, 1);
    node_agg_k<<<gb_node, 128>>>(We2, att2, bo2);

    // ---- final linear + relu -> d_out (fp32 out) ----
    gemm_tc_k<<<grid1, TB, GEMM_SMEM>>>(ph, wli, blin, out, wli, blin, out, Nn, 1, 0, 0);
}